// round 12
// baseline (speedup 1.0000x reference)
#include <cuda_runtime.h>
#include <math.h>
#include <stdint.h>

#define B_  8
#define N_  8192
#define C_  64
#define S_  2048
#define KNB 32
#define PTS (S_*KNB)
typedef unsigned long long ull;

__device__ float  g_featT[(size_t)B_*N_*C_];
__device__ float  g_centers[B_*3*S_];
__device__ int    g_nidx[B_*S_*KNB];
__device__ float  g_bufA[(size_t)B_*128*PTS];
__device__ float  g_bufB[(size_t)B_*128*PTS];
__device__ float  g_partS[4096*128];
__device__ float  g_partQ[4096*128];
__device__ double g_csum[2048];
__device__ double g_csq [2048];

__device__ __forceinline__ ull pk2(float lo, float hi) {
    ull r; asm("mov.b64 %0,{%1,%2};" : "=l"(r) : "f"(lo), "f"(hi)); return r;
}
__device__ __forceinline__ void upk2(ull v, float& lo, float& hi) {
    asm("mov.b64 {%0,%1},%2;" : "=f"(lo), "=f"(hi) : "l"(v));
}
__device__ __forceinline__ ull add2(ull a, ull b) {
    ull r; asm("add.rn.f32x2 %0,%1,%2;" : "=l"(r) : "l"(a), "l"(b)); return r;
}
__device__ __forceinline__ ull mul2(ull a, ull b) {
    ull r; asm("mul.rn.f32x2 %0,%1,%2;" : "=l"(r) : "l"(a), "l"(b)); return r;
}
__device__ __forceinline__ ull fma2(ull a, ull b, ull c) {
    ull r; asm("fma.rn.f32x2 %0,%1,%2,%3;" : "=l"(r) : "l"(a), "l"(b), "l"(c)); return r;
}

/* ------------ transpose features [b][c][n] -> [b][n][c] ------------ */
__global__ void k_transpose(const float* __restrict__ f) {
    __shared__ float t[32][33];
    int b = blockIdx.z;
    int nb = blockIdx.x * 32, cb = blockIdx.y * 32;
    int tx = threadIdx.x, ty = threadIdx.y;
#pragma unroll
    for (int j = 0; j < 32; j += 8)
        t[ty + j][tx] = f[((size_t)b*C_ + cb + ty + j)*N_ + nb + tx];
    __syncthreads();
#pragma unroll
    for (int j = 0; j < 32; j += 8)
        g_featT[((size_t)b*N_ + nb + ty + j)*C_ + cb + tx] = t[tx][ty + j];
}

/* ------------ FPS: one 512-thread block per batch (R6 proven) ------------ */
#define FPS_SMEM (3*N_*4 + 64*4)
__global__ void __launch_bounds__(512, 1) k_fps(const float* __restrict__ coords) {
    extern __shared__ float sm[];
    float* sx = sm; float* sy = sm + N_; float* sz = sm + 2*N_;
    unsigned* wbv = (unsigned*)(sm + 3*N_);
    unsigned* wbn = wbv + 32;
    int b = blockIdx.x, tid = threadIdx.x;
    int lane = tid & 31;
    int wid = tid >> 5;
    const float* cb = coords + (size_t)b*3*N_;

    ull pxp[8], pyp[8], pzp[8];
    float mind[16];
#pragma unroll
    for (int jj = 0; jj < 8; jj++) {
        int n0 = (2*jj)*512 + tid, n1 = n0 + 512;
        float x0 = cb[n0],        x1 = cb[n1];
        float y0 = cb[N_ + n0],   y1 = cb[N_ + n1];
        float z0 = cb[2*N_ + n0], z1 = cb[2*N_ + n1];
        sx[n0] = x0; sx[n1] = x1;
        sy[n0] = y0; sy[n1] = y1;
        sz[n0] = z0; sz[n1] = z1;
        pxp[jj] = pk2(x0, x1); pyp[jj] = pk2(y0, y1); pzp[jj] = pk2(z0, z1);
        mind[2*jj] = 1e10f; mind[2*jj+1] = 1e10f;
    }
    float lx = cb[0], ly = cb[N_], lz = cb[2*N_];
    if (tid == 0) {
        g_centers[(b*3+0)*S_] = lx;
        g_centers[(b*3+1)*S_] = ly;
        g_centers[(b*3+2)*S_] = lz;
    }
    __syncthreads();

    for (int step = 1; step < S_; ++step) {
        ull nlx = pk2(-lx, -lx), nly = pk2(-ly, -ly), nlz = pk2(-lz, -lz);
        float bd = -1.0f;
#pragma unroll
        for (int jj = 0; jj < 8; jj++) {
            ull dx = add2(pxp[jj], nlx);
            ull dy = add2(pyp[jj], nly);
            ull dz = add2(pzp[jj], nlz);
            ull s  = mul2(dx, dx);
            ull t  = mul2(dy, dy);
            s = add2(s, t);
            t = mul2(dz, dz);
            s = add2(s, t);
            float d0, d1; upk2(s, d0, d1);
            float m0 = fminf(mind[2*jj],   d0); mind[2*jj]   = m0;
            float m1 = fminf(mind[2*jj+1], d1); mind[2*jj+1] = m1;
            bd = fmaxf(bd, m0);
            bd = fmaxf(bd, m1);
        }
        unsigned bdb = __float_as_uint(bd);
        unsigned wv  = __reduce_max_sync(0xffffffffu, bdb);
        unsigned cand = 0xffffffffu;
        if (bdb == wv) {
#pragma unroll
            for (int j = 15; j >= 0; j--)
                if (__float_as_uint(mind[j]) == wv)
                    cand = (unsigned)(j*512 + tid);
        }
        unsigned wn = __reduce_min_sync(0xffffffffu, cand);
        int pb = (step & 1) * 16;
        if (lane == 0) { wbv[pb + wid] = wv; wbn[pb + wid] = wn; }
        __syncthreads();
        unsigned v  = wbv[pb + (lane & 15)];
        unsigned nn = wbn[pb + (lane & 15)];
        unsigned vm = __reduce_max_sync(0xffffffffu, v);
        unsigned c2 = (v == vm) ? nn : 0xffffffffu;
        unsigned win = __reduce_min_sync(0xffffffffu, c2);
        lx = sx[win]; ly = sy[win]; lz = sz[win];
        if (tid == 0) {
            g_centers[(b*3+0)*S_ + step] = lx;
            g_centers[(b*3+1)*S_ + step] = ly;
            g_centers[(b*3+2)*S_ + step] = lz;
        }
    }
}

/* ------------ ball query: warp per center ------------ */
#define BALL_SMEM (3*N_*4)
__global__ void __launch_bounds__(256) k_ball(const float* __restrict__ coords) {
    extern __shared__ float sm[];
    float* sx = sm; float* sy = sm + N_; float* sz = sm + 2*N_;
    int blk = blockIdx.x;
    int b = blk >> 5, part = blk & 31;
    int tid = threadIdx.x;
    const float* cb = coords + (size_t)b*3*N_;
    for (int n = tid; n < N_; n += 256) {
        sx[n] = cb[n]; sy[n] = cb[N_ + n]; sz[n] = cb[2*N_ + n];
    }
    __syncthreads();
    int w = tid >> 5, lane = tid & 31;
    for (int cc = 0; cc < 8; cc++) {
        int s = part*64 + w*8 + cc;
        float cx = g_centers[(b*3+0)*S_ + s];
        float cy = g_centers[(b*3+1)*S_ + s];
        float cz = g_centers[(b*3+2)*S_ + s];
        float cn = __fadd_rn(__fadd_rn(__fmul_rn(cx,cx), __fmul_rn(cy,cy)), __fmul_rn(cz,cz));
        int found = 0, firstn = 0;
        int* op = &g_nidx[((size_t)b*S_ + s)*KNB];
        for (int base = 0; base < N_; base += 32) {
            int n = base + lane;
            float x = sx[n], y = sy[n], z = sz[n];
            float pn = __fadd_rn(__fadd_rn(__fmul_rn(x,x), __fmul_rn(y,y)), __fmul_rn(z,z));
            float cp = __fadd_rn(__fadd_rn(__fmul_rn(cx,x), __fmul_rn(cy,y)), __fmul_rn(cz,z));
            float d2 = __fsub_rn(__fadd_rn(cn, pn), __fmul_rn(2.0f, cp));
            bool hit = d2 < 0.0625f;
            unsigned bal = __ballot_sync(0xffffffffu, hit);
            if (bal) {
                if (found == 0) firstn = base + __ffs(bal) - 1;
                int slot = found + __popc(bal & ((1u << lane) - 1u));
                if (hit && slot < KNB) op[slot] = n;
                found += __popc(bal);
                if (found >= KNB) break;
            }
        }
        if (found < KNB) {
            int fill = (found > 0) ? firstn : 0;
            for (int sl = found + lane; sl < KNB; sl += 32) op[sl] = fill;
        }
    }
}

/* ---- partial-stats epilogue: skewed [ch][64] arrays aliased into dead smem ---- */
__device__ __forceinline__ void emit_partials(
    const ull* acc0, const ull* acc1, float* psS, float* psQ,
    int og, int l, int nq) {
#pragma unroll
    for (int q = 0; q < 16; q++) {
        if (q >= nq) break;
        int o = og*32 + 2*q;
        ull sp = add2(acc0[q], acc1[q]);
        ull m  = mul2(acc0[q], acc0[q]);
        ull qp = fma2(acc1[q], acc1[q], m);
        float s0, s1, q0, q1;
        upk2(sp, s0, s1); upk2(qp, q0, q1);
        psS[o*64     + ((l + o)     & 63)] = s0;
        psS[(o+1)*64 + ((l + o + 1) & 63)] = s1;
        psQ[o*64     + ((l + o)     & 63)] = q0;
        psQ[(o+1)*64 + ((l + o + 1) & 63)] = q1;
    }
}

/* ------------ conv0: gather + (67->64), 2 og x 2 pts, fused stats ------------ */
#define CONV0_SMEM (68*128*4 + 68*32*8 + 64*4)
__global__ void __launch_bounds__(128) k_conv0(const float* __restrict__ coords,
                                               const float* __restrict__ w0,
                                               const float* __restrict__ b0) {
    extern __shared__ float sm[];
    float* xs = sm;                       /* [68][128] */
    ull*   wp = (ull*)(sm + 68*128);      /* [68][32] packed out-pairs */
    float* bs = (float*)(wp + 68*32);
    int tid = threadIdx.x;
    int b = blockIdx.x >> 9;
    int pb = blockIdx.x & 511;
    int pbase = pb*128;
    int p = pbase + tid;

    for (int k2 = tid; k2 < 68*32; k2 += 128) {
        int i = k2 >> 5, o2 = k2 & 31;
        float a = (i < 67) ? w0[(2*o2)*67 + i]   : 0.0f;
        float c = (i < 67) ? w0[(2*o2+1)*67 + i] : 0.0f;
        wp[k2] = pk2(a, c);
    }
    if (tid < 64) bs[tid] = b0[tid];

    int s = p >> 5;
    int n = g_nidx[((size_t)b*S_ + s)*KNB + (p & 31)];
    const float* cb = coords + (size_t)b*3*N_;
    xs[0*128 + tid] = __fsub_rn(cb[n],        g_centers[(b*3+0)*S_ + s]);
    xs[1*128 + tid] = __fsub_rn(cb[N_ + n],   g_centers[(b*3+1)*S_ + s]);
    xs[2*128 + tid] = __fsub_rn(cb[2*N_ + n], g_centers[(b*3+2)*S_ + s]);
    const float4* fp = (const float4*)(g_featT + ((size_t)b*N_ + n)*C_);
#pragma unroll
    for (int q = 0; q < 16; q++) {
        float4 v = fp[q]; int ib = 3 + 4*q;
        xs[(ib+0)*128 + tid] = v.x; xs[(ib+1)*128 + tid] = v.y;
        xs[(ib+2)*128 + tid] = v.z; xs[(ib+3)*128 + tid] = v.w;
    }
    xs[67*128 + tid] = 0.0f;
    __syncthreads();

    int og  = tid >> 6;            /* 0..1 */
    int l   = tid & 63;
    int pt0 = l * 2;
    ull acc0[16], acc1[16];
#pragma unroll
    for (int q = 0; q < 16; q++) {
        ull bv = pk2(bs[og*32 + 2*q], bs[og*32 + 2*q + 1]);
        acc0[q] = bv; acc1[q] = bv;
    }
#pragma unroll 2
    for (int i = 0; i < 68; i++) {
        ull xv = *(const ull*)(xs + i*128 + pt0);
        float x0, x1; upk2(xv, x0, x1);
        ull xx0 = pk2(x0, x0), xx1 = pk2(x1, x1);
        const ulonglong2* wr = (const ulonglong2*)(wp + i*32 + og*16);
#pragma unroll
        for (int q = 0; q < 8; q++) {
            ulonglong2 wq = wr[q];
            acc0[2*q]   = fma2(wq.x, xx0, acc0[2*q]);
            acc1[2*q]   = fma2(wq.x, xx1, acc1[2*q]);
            acc0[2*q+1] = fma2(wq.y, xx0, acc0[2*q+1]);
            acc1[2*q+1] = fma2(wq.y, xx1, acc1[2*q+1]);
        }
    }
    float* yb = g_bufA + ((size_t)b*64)*PTS + pbase + pt0;
#pragma unroll
    for (int q = 0; q < 16; q++) {
        int o = og*32 + 2*q;
        float a00, a01, a10, a11;
        upk2(acc0[q], a00, a01);
        upk2(acc1[q], a10, a11);
        *(float2*)(yb + (size_t)o*PTS)     = make_float2(a00, a10);
        *(float2*)(yb + (size_t)(o+1)*PTS) = make_float2(a01, a11);
    }
    /* fused stats: reuse xs as skewed [64][64] partial arrays */
    __syncthreads();
    float* psS = sm;
    float* psQ = sm + 64*64;
    emit_partials(acc0, acc1, psS, psQ, og, l, 16);
    __syncthreads();
    if (tid < 64) {
        float ss = 0.0f, qq = 0.0f;
        for (int k = 0; k < 64; k++) {
            int col = (tid + k) & 63;
            ss += psS[tid*64 + col];
            qq += psQ[tid*64 + col];
        }
        g_partS[((size_t)b*64 + tid)*512 + pb] = ss;
        g_partQ[((size_t)b*64 + tid)*512 + pb] = qq;
    }
}

/* ------------ k_red: 512 block-partials -> g_csum/g_csq (deterministic) ------------ */
__global__ void __launch_bounds__(256) k_red(int off) {
    int bc = blockIdx.x;
    int t = threadIdx.x;
    const float* pS = g_partS + (size_t)bc*512;
    const float* pQ = g_partQ + (size_t)bc*512;
    double ds = (double)pS[t] + (double)pS[t + 256];
    double dq = (double)pQ[t] + (double)pQ[t + 256];
    int lane = t & 31, w = t >> 5;
#pragma unroll
    for (int o = 16; o; o >>= 1) {
        ds += __shfl_xor_sync(0xffffffffu, ds, o);
        dq += __shfl_xor_sync(0xffffffffu, dq, o);
    }
    __shared__ double sh[16];
    if (lane == 0) { sh[w] = ds; sh[8 + w] = dq; }
    __syncthreads();
    if (t == 0) {
        double S = 0.0, Q = 0.0;
#pragma unroll
        for (int i = 0; i < 8; i++) { S += sh[i]; Q += sh[8 + i]; }
        g_csum[off + bc] = S; g_csq[off + bc] = Q;
    }
}

/* ------------ convN64: GN + SiLU + (64->64), 2 og x 2 pts, fused stats ------------ */
#define CONVN64_SMEM (64*128*4 + 64*32*8 + (64+64+64)*4)
__global__ void __launch_bounds__(128) k_convN64(const float* __restrict__ w,
                                                 const float* __restrict__ bb,
                                                 const float* __restrict__ gamma,
                                                 const float* __restrict__ beta,
                                                 int off, double inv_cnt) {
    extern __shared__ float sm[];
    float* xs = sm;                        /* [64][128] */
    ull*   wp = (ull*)(sm + 64*128);       /* [64][32] */
    float* bs = (float*)(wp + 64*32);
    float* al = bs + 64;
    float* bt = al + 64;
    int tid = threadIdx.x;
    int b = blockIdx.x >> 9;
    int pb = blockIdx.x & 511;
    int pbase = pb*128;
    int p = pbase + tid;

    for (int k2 = tid; k2 < 64*32; k2 += 128) {
        int i = k2 >> 5, o2 = k2 & 31;
        wp[k2] = pk2(w[(2*o2)*64 + i], w[(2*o2+1)*64 + i]);
    }
    if (tid < 64) bs[tid] = bb[tid];
    if (tid < 64) {
        int g = tid >> 3;
        double ms = 0.0, qs = 0.0;
#pragma unroll
        for (int cc = 0; cc < 8; cc++) {
            ms += g_csum[off + b*64 + g*8 + cc];
            qs += g_csq [off + b*64 + g*8 + cc];
        }
        double mu  = ms * inv_cnt;
        double var = qs * inv_cnt - mu*mu;
        float rstd = (float)rsqrt(var + 1e-5);
        float a = gamma[tid] * rstd;
        al[tid] = a;
        bt[tid] = beta[tid] - (float)mu * a;
    }
    __syncthreads();

#pragma unroll 1
    for (int ci = 0; ci < 64; ci++) {
        float v  = g_bufA[((size_t)b*64 + ci)*PTS + p];
        float xn = fmaf(v, al[ci], bt[ci]);
        float sg = __fdividef(1.0f, 1.0f + __expf(-xn));
        xs[ci*128 + tid] = xn * sg;
    }
    __syncthreads();

    int og  = tid >> 6;
    int l   = tid & 63;
    int pt0 = l * 2;
    ull acc0[16], acc1[16];
#pragma unroll
    for (int q = 0; q < 16; q++) {
        ull bv = pk2(bs[og*32 + 2*q], bs[og*32 + 2*q + 1]);
        acc0[q] = bv; acc1[q] = bv;
    }
#pragma unroll 2
    for (int i = 0; i < 64; i++) {
        ull xv = *(const ull*)(xs + i*128 + pt0);
        float x0, x1; upk2(xv, x0, x1);
        ull xx0 = pk2(x0, x0), xx1 = pk2(x1, x1);
        const ulonglong2* wr = (const ulonglong2*)(wp + i*32 + og*16);
#pragma unroll
        for (int q = 0; q < 8; q++) {
            ulonglong2 wq = wr[q];
            acc0[2*q]   = fma2(wq.x, xx0, acc0[2*q]);
            acc1[2*q]   = fma2(wq.x, xx1, acc1[2*q]);
            acc0[2*q+1] = fma2(wq.y, xx0, acc0[2*q+1]);
            acc1[2*q+1] = fma2(wq.y, xx1, acc1[2*q+1]);
        }
    }
    float* yb = g_bufB + ((size_t)b*64)*PTS + pbase + pt0;
#pragma unroll
    for (int q = 0; q < 16; q++) {
        int o = og*32 + 2*q;
        float a00, a01, a10, a11;
        upk2(acc0[q], a00, a01);
        upk2(acc1[q], a10, a11);
        *(float2*)(yb + (size_t)o*PTS)     = make_float2(a00, a10);
        *(float2*)(yb + (size_t)(o+1)*PTS) = make_float2(a01, a11);
    }
    __syncthreads();
    float* psS = sm;
    float* psQ = sm + 64*64;
    emit_partials(acc0, acc1, psS, psQ, og, l, 16);
    __syncthreads();
    if (tid < 64) {
        float ss = 0.0f, qq = 0.0f;
        for (int k = 0; k < 64; k++) {
            int col = (tid + k) & 63;
            ss += psS[tid*64 + col];
            qq += psQ[tid*64 + col];
        }
        g_partS[((size_t)b*64 + tid)*512 + pb] = ss;
        g_partQ[((size_t)b*64 + tid)*512 + pb] = qq;
    }
}

/* ------------ conv128: GN + SiLU + (64->128), 256 thr, 4 og x 2 pts, fused stats ------------ */
#define CONV128_SMEM (64*128*4 + 64*64*8 + (128+64+64)*4)
__global__ void __launch_bounds__(256) k_conv128(const float* __restrict__ w,
                                                 const float* __restrict__ bb,
                                                 const float* __restrict__ gamma,
                                                 const float* __restrict__ beta,
                                                 int off, double inv_cnt) {
    extern __shared__ float sm[];
    float* xs = sm;                        /* [64][128] */
    ull*   wp = (ull*)(sm + 64*128);       /* [64][64] out-pairs */
    float* bs = (float*)(wp + 64*64);      /* [128] */
    float* al = bs + 128;
    float* bt = al + 64;
    int tid = threadIdx.x;
    int b = blockIdx.x >> 9;
    int pb = blockIdx.x & 511;
    int pbase = pb*128;

    for (int k2 = tid; k2 < 64*64; k2 += 256) {
        int i = k2 >> 6, o2 = k2 & 63;
        wp[k2] = pk2(w[(2*o2)*64 + i], w[(2*o2+1)*64 + i]);
    }
    if (tid < 128) bs[tid] = bb[tid];
    if (tid < 64) {
        int g = tid >> 3;
        double ms = 0.0, qs = 0.0;
#pragma unroll
        for (int cc = 0; cc < 8; cc++) {
            ms += g_csum[off + b*64 + g*8 + cc];
            qs += g_csq [off + b*64 + g*8 + cc];
        }
        double mu  = ms * inv_cnt;
        double var = qs * inv_cnt - mu*mu;
        float rstd = (float)rsqrt(var + 1e-5);
        float a = gamma[tid] * rstd;
        al[tid] = a;
        bt[tid] = beta[tid] - (float)mu * a;
    }
    __syncthreads();

    {
        int h = tid >> 7, pt = tid & 127;
        int p = pbase + pt;
#pragma unroll 1
        for (int cc = 0; cc < 32; cc++) {
            int ci = h*32 + cc;
            float v  = g_bufB[((size_t)b*64 + ci)*PTS + p];
            float xn = fmaf(v, al[ci], bt[ci]);
            float sg = __fdividef(1.0f, 1.0f + __expf(-xn));
            xs[ci*128 + pt] = xn * sg;
        }
    }
    __syncthreads();

    int og  = tid >> 6;            /* 0..3 */
    int l   = tid & 63;
    int pt0 = l * 2;
    ull acc0[16], acc1[16];
#pragma unroll
    for (int q = 0; q < 16; q++) {
        ull bv = pk2(bs[og*32 + 2*q], bs[og*32 + 2*q + 1]);
        acc0[q] = bv; acc1[q] = bv;
    }
#pragma unroll 2
    for (int i = 0; i < 64; i++) {
        ull xv = *(const ull*)(xs + i*128 + pt0);
        float x0, x1; upk2(xv, x0, x1);
        ull xx0 = pk2(x0, x0), xx1 = pk2(x1, x1);
        const ulonglong2* wr = (const ulonglong2*)(wp + i*64 + og*16);
#pragma unroll
        for (int q = 0; q < 8; q++) {
            ulonglong2 wq = wr[q];
            acc0[2*q]   = fma2(wq.x, xx0, acc0[2*q]);
            acc1[2*q]   = fma2(wq.x, xx1, acc1[2*q]);
            acc0[2*q+1] = fma2(wq.y, xx0, acc0[2*q+1]);
            acc1[2*q+1] = fma2(wq.y, xx1, acc1[2*q+1]);
        }
    }
    float* yb = g_bufA + ((size_t)b*128)*PTS + pbase + pt0;
#pragma unroll
    for (int q = 0; q < 16; q++) {
        int o = og*32 + 2*q;
        float a00, a01, a10, a11;
        upk2(acc0[q], a00, a01);
        upk2(acc1[q], a10, a11);
        *(float2*)(yb + (size_t)o*PTS)     = make_float2(a00, a10);
        *(float2*)(yb + (size_t)(o+1)*PTS) = make_float2(a01, a11);
    }
    /* fused stats: psS in xs, psQ in wp (both dead) */
    __syncthreads();
    float* psS = sm;                 /* [128][64] skewed = 32KB */
    float* psQ = sm + 128*64;        /* [128][64] skewed = 32KB (wp region) */
    emit_partials(acc0, acc1, psS, psQ, og, l, 16);
    __syncthreads();
    if (tid < 128) {
        float ss = 0.0f, qq = 0.0f;
        for (int k = 0; k < 64; k++) {
            int col = (tid + k) & 63;
            ss += psS[tid*64 + col];
            qq += psQ[tid*64 + col];
        }
        g_partS[((size_t)b*128 + tid)*512 + pb] = ss;
        g_partQ[((size_t)b*128 + tid)*512 + pb] = qq;
    }
}

/* ------------ final: GN + SiLU + max over K ------------ */
__global__ void __launch_bounds__(256) k_final(const float* __restrict__ gamma,
                                               const float* __restrict__ beta,
                                               float* __restrict__ out,
                                               int off, double inv_cnt) {
    int blk = blockIdx.x;
    int bc = blk >> 5;
    int chunk = blk & 31;
    int b = bc >> 7, c = bc & 127;
    __shared__ float s_a, s_b;
    if (threadIdx.x == 0) {
        int g = c >> 4;
        double ms = 0.0, qs = 0.0;
#pragma unroll
        for (int cc = 0; cc < 16; cc++) {
            ms += g_csum[off + b*128 + g*16 + cc];
            qs += g_csq [off + b*128 + g*16 + cc];
        }
        double mu  = ms * inv_cnt;
        double var = qs * inv_cnt - mu*mu;
        float rstd = (float)rsqrt(var + 1e-5);
        float a = gamma[c] * rstd;
        s_a = a;
        s_b = beta[c] - (float)mu * a;
    }
    __syncthreads();
    float a = s_a, bt = s_b;
    int w = threadIdx.x >> 5, lane = threadIdx.x & 31;
    const float* base = g_bufA + (size_t)bc*PTS;
#pragma unroll 1
    for (int j = 0; j < 8; j++) {
        int s = chunk*64 + w*8 + j;
        float v  = base[s*32 + lane];
        float xn = fmaf(v, a, bt);
        float sg = __fdividef(1.0f, 1.0f + __expf(-xn));
        float val = xn * sg;
#pragma unroll
        for (int o = 16; o; o >>= 1)
            val = fmaxf(val, __shfl_xor_sync(0xffffffffu, val, o));
        if (lane == 0) out[(size_t)bc*S_ + s] = val;
    }
}

extern "C" void kernel_launch(void* const* d_in, const int* in_sizes, int n_in,
                              void* d_out, int out_size) {
    const float* coords   = (const float*)d_in[0];
    const float* features = (const float*)d_in[1];
    const float* w0 = (const float*)d_in[2];
    const float* b0 = (const float*)d_in[3];
    const float* g0 = (const float*)d_in[4];
    const float* be0= (const float*)d_in[5];
    const float* w1 = (const float*)d_in[6];
    const float* b1 = (const float*)d_in[7];
    const float* g1 = (const float*)d_in[8];
    const float* be1= (const float*)d_in[9];
    const float* w2 = (const float*)d_in[10];
    const float* b2 = (const float*)d_in[11];
    const float* g2 = (const float*)d_in[12];
    const float* be2= (const float*)d_in[13];
    float* out = (float*)d_out;

    cudaFuncSetAttribute(k_fps,     cudaFuncAttributeMaxDynamicSharedMemorySize, FPS_SMEM);
    cudaFuncSetAttribute(k_ball,    cudaFuncAttributeMaxDynamicSharedMemorySize, BALL_SMEM);
    cudaFuncSetAttribute(k_conv0,   cudaFuncAttributeMaxDynamicSharedMemorySize, CONV0_SMEM);
    cudaFuncSetAttribute(k_convN64, cudaFuncAttributeMaxDynamicSharedMemorySize, CONVN64_SMEM);
    cudaFuncSetAttribute(k_conv128, cudaFuncAttributeMaxDynamicSharedMemorySize, CONV128_SMEM);

    dim3 tg(N_/32, C_/32, B_);
    k_transpose<<<tg, dim3(32,8)>>>(features);
    k_fps<<<B_, 512, FPS_SMEM>>>(coords);
    k_ball<<<B_*32, 256, BALL_SMEM>>>(coords);
    k_conv0<<<B_*512, 128, CONV0_SMEM>>>(coords, w0, b0);
    k_red<<<B_*64, 256>>>(0);
    k_convN64<<<B_*512, 128, CONVN64_SMEM>>>(w1, b1, g0, be0, 0, 1.0/(8.0*PTS));
    k_red<<<B_*64, 256>>>(512);
    k_conv128<<<B_*512, 256, CONV128_SMEM>>>(w2, b2, g1, be1, 512, 1.0/(8.0*PTS));
    k_red<<<B_*128, 256>>>(1024);
    k_final<<<B_*128*32, 256>>>(g2, be2, out, 1024, 1.0/(16.0*PTS));
}

// round 13
// speedup vs baseline: 1.0798x; 1.0798x over previous
#include <cuda_runtime.h>
#include <math.h>
#include <stdint.h>

#define B_  8
#define N_  8192
#define C_  64
#define S_  2048
#define KNB 32
#define PTS (S_*KNB)
typedef unsigned long long ull;

__device__ float    g_featT[(size_t)B_*N_*C_];
__device__ float    g_centers[B_*3*S_];
__device__ float    g_bufA[(size_t)B_*128*PTS];
__device__ float    g_bufB[(size_t)B_*128*PTS];
__device__ double   g_csum[2048];
__device__ double   g_csq [2048];
__device__ unsigned g_prog[8];

__device__ __forceinline__ ull pk2(float lo, float hi) {
    ull r; asm("mov.b64 %0,{%1,%2};" : "=l"(r) : "f"(lo), "f"(hi)); return r;
}
__device__ __forceinline__ void upk2(ull v, float& lo, float& hi) {
    asm("mov.b64 {%0,%1},%2;" : "=f"(lo), "=f"(hi) : "l"(v));
}
__device__ __forceinline__ ull add2(ull a, ull b) {
    ull r; asm("add.rn.f32x2 %0,%1,%2;" : "=l"(r) : "l"(a), "l"(b)); return r;
}
__device__ __forceinline__ ull mul2(ull a, ull b) {
    ull r; asm("mul.rn.f32x2 %0,%1,%2;" : "=l"(r) : "l"(a), "l"(b)); return r;
}
__device__ __forceinline__ ull fma2(ull a, ull b, ull c) {
    ull r; asm("fma.rn.f32x2 %0,%1,%2,%3;" : "=l"(r) : "l"(a), "l"(b), "l"(c)); return r;
}

/* ------------ transpose features [b][c][n] -> [b][n][c] ------------ */
__global__ void k_transpose(const float* __restrict__ f) {
    __shared__ float t[32][33];
    int b = blockIdx.z;
    int nb = blockIdx.x * 32, cb = blockIdx.y * 32;
    int tx = threadIdx.x, ty = threadIdx.y;
#pragma unroll
    for (int j = 0; j < 32; j += 8)
        t[ty + j][tx] = f[((size_t)b*C_ + cb + ty + j)*N_ + nb + tx];
    __syncthreads();
#pragma unroll
    for (int j = 0; j < 32; j += 8)
        g_featT[((size_t)b*N_ + nb + ty + j)*C_ + cb + tx] = t[tx][ty + j];
}

/* ------------ fused: FPS (blocks 0-7) + ball/conv0 workers (blocks 8+) ------------ */
#define FUSED_SMEM (3*N_*4 + 64*4)   /* 98560 B; worker layout fits inside */
__global__ void __launch_bounds__(512, 1) k_fused(const float* __restrict__ coords,
                                                  const float* __restrict__ w0,
                                                  const float* __restrict__ b0) {
    extern __shared__ float sm[];
    int tid = threadIdx.x;
    int lane = tid & 31, wid = tid >> 5;

    if (blockIdx.x < 8) {
        /* ================= FPS producer (R6-proven) ================= */
        float* sx = sm; float* sy = sm + N_; float* sz = sm + 2*N_;
        unsigned* wbv = (unsigned*)(sm + 3*N_);
        unsigned* wbn = wbv + 32;
        int b = blockIdx.x;
        const float* cb = coords + (size_t)b*3*N_;

        ull pxp[8], pyp[8], pzp[8];
        float mind[16];
#pragma unroll
        for (int jj = 0; jj < 8; jj++) {
            int n0 = (2*jj)*512 + tid, n1 = n0 + 512;
            float x0 = cb[n0],        x1 = cb[n1];
            float y0 = cb[N_ + n0],   y1 = cb[N_ + n1];
            float z0 = cb[2*N_ + n0], z1 = cb[2*N_ + n1];
            sx[n0] = x0; sx[n1] = x1;
            sy[n0] = y0; sy[n1] = y1;
            sz[n0] = z0; sz[n1] = z1;
            pxp[jj] = pk2(x0, x1); pyp[jj] = pk2(y0, y1); pzp[jj] = pk2(z0, z1);
            mind[2*jj] = 1e10f; mind[2*jj+1] = 1e10f;
        }
        float lx = cb[0], ly = cb[N_], lz = cb[2*N_];
        if (tid == 0) {
            g_centers[(b*3+0)*S_] = lx;
            g_centers[(b*3+1)*S_] = ly;
            g_centers[(b*3+2)*S_] = lz;
        }
        __syncthreads();

        for (int step = 1; step < S_; ++step) {
            ull nlx = pk2(-lx, -lx), nly = pk2(-ly, -ly), nlz = pk2(-lz, -lz);
            float bd = -1.0f;
#pragma unroll
            for (int jj = 0; jj < 8; jj++) {
                ull dx = add2(pxp[jj], nlx);
                ull dy = add2(pyp[jj], nly);
                ull dz = add2(pzp[jj], nlz);
                ull s  = mul2(dx, dx);
                ull t  = mul2(dy, dy);
                s = add2(s, t);
                t = mul2(dz, dz);
                s = add2(s, t);
                float d0, d1; upk2(s, d0, d1);
                float m0 = fminf(mind[2*jj],   d0); mind[2*jj]   = m0;
                float m1 = fminf(mind[2*jj+1], d1); mind[2*jj+1] = m1;
                bd = fmaxf(bd, m0);
                bd = fmaxf(bd, m1);
            }
            unsigned bdb = __float_as_uint(bd);
            unsigned wv  = __reduce_max_sync(0xffffffffu, bdb);
            unsigned cand = 0xffffffffu;
            if (bdb == wv) {
#pragma unroll
                for (int j = 15; j >= 0; j--)
                    if (__float_as_uint(mind[j]) == wv)
                        cand = (unsigned)(j*512 + tid);
            }
            unsigned wn = __reduce_min_sync(0xffffffffu, cand);
            int pb = (step & 1) * 16;
            if (lane == 0) { wbv[pb + wid] = wv; wbn[pb + wid] = wn; }
            __syncthreads();
            unsigned v  = wbv[pb + (lane & 15)];
            unsigned nn = wbn[pb + (lane & 15)];
            unsigned vm = __reduce_max_sync(0xffffffffu, v);
            unsigned c2 = (v == vm) ? nn : 0xffffffffu;
            unsigned win = __reduce_min_sync(0xffffffffu, c2);
            lx = sx[win]; ly = sy[win]; lz = sz[win];
            if (tid == 0) {
                g_centers[(b*3+0)*S_ + step] = lx;
                g_centers[(b*3+1)*S_ + step] = ly;
                g_centers[(b*3+2)*S_ + step] = lz;
                if ((step & 15) == 15) {
                    unsigned pv = (unsigned)(step + 1);
                    asm volatile("st.release.gpu.u32 [%0], %1;"
                                 :: "l"(g_prog + b), "r"(pv) : "memory");
                }
            }
        }
    } else {
        /* ================= ball + conv0 consumer ================= */
        int w = blockIdx.x - 8;
        int b = w & 7;
        int cbase = (w >> 3) * 16;          /* 16 centers per worker */
        float* xs = sm;                     /* [68][256] */
        ull*   wp = (ull*)(sm + 68*256);    /* [68][32] packed out-pairs */
        float* bs = (float*)(wp + 68*32);   /* [64] */
        float* cs = bs + 64;                /* [3][16] centers */
        int*   ns = (int*)(cs + 48);        /* [16][32] neighbor idx */
        const float* cb = coords + (size_t)b*3*N_;

        /* stage weights/bias while producer runs */
        for (int k2 = tid; k2 < 68*32; k2 += 512) {
            int i = k2 >> 5, o2 = k2 & 31;
            float a = (i < 67) ? w0[(2*o2)*67 + i]   : 0.0f;
            float c = (i < 67) ? w0[(2*o2+1)*67 + i] : 0.0f;
            wp[k2] = pk2(a, c);
        }
        if (tid < 64) bs[tid] = b0[tid];

        /* wait for our 16 centers */
        if (tid == 0) {
            unsigned target = (unsigned)(cbase + 16);
            for (;;) {
                unsigned v;
                asm volatile("ld.acquire.gpu.u32 %0, [%1];"
                             : "=r"(v) : "l"(g_prog + b) : "memory");
                if (v >= target) break;
                __nanosleep(1000);
            }
        }
        __syncthreads();
        if (tid < 48) {
            int d = tid >> 4, s = cbase + (tid & 15);
            cs[tid] = g_centers[(b*3 + d)*S_ + s];
        }
        __syncthreads();

        /* ball query: warp per center (bit-exact same math as before) */
        {
            float cx = cs[wid], cy = cs[16 + wid], cz = cs[32 + wid];
            float cn = __fadd_rn(__fadd_rn(__fmul_rn(cx,cx), __fmul_rn(cy,cy)), __fmul_rn(cz,cz));
            int found = 0, firstn = 0;
            int* op = ns + wid*KNB;
            for (int base = 0; base < N_; base += 32) {
                int n = base + lane;
                float x = __ldg(cb + n), y = __ldg(cb + N_ + n), z = __ldg(cb + 2*N_ + n);
                float pn = __fadd_rn(__fadd_rn(__fmul_rn(x,x), __fmul_rn(y,y)), __fmul_rn(z,z));
                float cp = __fadd_rn(__fadd_rn(__fmul_rn(cx,x), __fmul_rn(cy,y)), __fmul_rn(cz,z));
                float d2 = __fsub_rn(__fadd_rn(cn, pn), __fmul_rn(2.0f, cp));
                bool hit = d2 < 0.0625f;
                unsigned bal = __ballot_sync(0xffffffffu, hit);
                if (bal) {
                    if (found == 0) firstn = base + __ffs(bal) - 1;
                    int slot = found + __popc(bal & ((1u << lane) - 1u));
                    if (hit && slot < KNB) op[slot] = n;
                    found += __popc(bal);
                    if (found >= KNB) break;
                }
            }
            if (found < KNB) {
                int fill = (found > 0) ? firstn : 0;
                for (int sl = found + lane; sl < KNB; sl += 32) op[sl] = fill;
            }
        }
        __syncthreads();

        /* conv0 over 512 points in two 256-pt tiles (bit-exact same acc order) */
        for (int tile = 0; tile < 2; tile++) {
            int pb2 = tile * 256;
            {
                int h = tid >> 8, pt = tid & 255;
                int lp = pb2 + pt;
                int sl = lp >> 5;
                int n = ns[sl*KNB + (lp & 31)];
                const float4* fp = (const float4*)(g_featT + ((size_t)b*N_ + n)*C_);
                if (h == 0) {
                    xs[0*256 + pt] = __fsub_rn(cb[n],        cs[sl]);
                    xs[1*256 + pt] = __fsub_rn(cb[N_ + n],   cs[16 + sl]);
                    xs[2*256 + pt] = __fsub_rn(cb[2*N_ + n], cs[32 + sl]);
#pragma unroll
                    for (int q = 0; q < 8; q++) {
                        float4 v = fp[q]; int ib = 3 + 4*q;
                        xs[(ib+0)*256 + pt] = v.x; xs[(ib+1)*256 + pt] = v.y;
                        xs[(ib+2)*256 + pt] = v.z; xs[(ib+3)*256 + pt] = v.w;
                    }
                } else {
#pragma unroll
                    for (int q = 8; q < 16; q++) {
                        float4 v = fp[q]; int ib = 3 + 4*q;
                        xs[(ib+0)*256 + pt] = v.x; xs[(ib+1)*256 + pt] = v.y;
                        xs[(ib+2)*256 + pt] = v.z; xs[(ib+3)*256 + pt] = v.w;
                    }
                    xs[67*256 + pt] = 0.0f;
                }
            }
            __syncthreads();

            int og  = tid >> 7;           /* 0..3: outputs og*16..og*16+15 */
            int pr  = tid & 127;
            int pt0 = pr * 2;
            ull acc0[8], acc1[8];
#pragma unroll
            for (int q = 0; q < 8; q++) {
                ull bv = pk2(bs[og*16 + 2*q], bs[og*16 + 2*q + 1]);
                acc0[q] = bv; acc1[q] = bv;
            }
#pragma unroll 2
            for (int i = 0; i < 68; i++) {
                ull xv = *(const ull*)(xs + i*256 + pt0);
                float x0, x1; upk2(xv, x0, x1);
                ull xx0 = pk2(x0, x0), xx1 = pk2(x1, x1);
                const ulonglong2* wr = (const ulonglong2*)(wp + i*32 + og*8);
#pragma unroll
                for (int q2 = 0; q2 < 4; q2++) {
                    ulonglong2 wq = wr[q2];
                    acc0[2*q2]   = fma2(wq.x, xx0, acc0[2*q2]);
                    acc1[2*q2]   = fma2(wq.x, xx1, acc1[2*q2]);
                    acc0[2*q2+1] = fma2(wq.y, xx0, acc0[2*q2+1]);
                    acc1[2*q2+1] = fma2(wq.y, xx1, acc1[2*q2+1]);
                }
            }
            float* yb = g_bufA + ((size_t)b*64)*PTS + cbase*KNB + pb2 + pt0;
#pragma unroll
            for (int q = 0; q < 8; q++) {
                int o = og*16 + 2*q;
                float a00, a01, a10, a11;
                upk2(acc0[q], a00, a01);
                upk2(acc1[q], a10, a11);
                *(float2*)(yb + (size_t)o*PTS)     = make_float2(a00, a10);
                *(float2*)(yb + (size_t)(o+1)*PTS) = make_float2(a01, a11);
            }
            __syncthreads();
        }
    }
}

/* ------------ per-(b,c) stats: deterministic two-stage ------------ */
template<int COUT, bool SRC_A>
__global__ void __launch_bounds__(256) k_stats(int off) {
    const float* y = SRC_A ? g_bufA : g_bufB;
    int bc = blockIdx.x;
    const float4* p4 = (const float4*)(y + (size_t)bc*PTS);
    float s = 0.0f, q = 0.0f;
    for (int i = threadIdx.x; i < PTS/4; i += 256) {
        float4 v = p4[i];
        s += v.x + v.y + v.z + v.w;
        q += v.x*v.x + v.y*v.y + v.z*v.z + v.w*v.w;
    }
    double ds = (double)s, dq = (double)q;
    int lane = threadIdx.x & 31, w = threadIdx.x >> 5;
#pragma unroll
    for (int o = 16; o; o >>= 1) {
        ds += __shfl_xor_sync(0xffffffffu, ds, o);
        dq += __shfl_xor_sync(0xffffffffu, dq, o);
    }
    __shared__ double sh[16];
    if (lane == 0) { sh[w] = ds; sh[8 + w] = dq; }
    __syncthreads();
    if (threadIdx.x == 0) {
        double S = 0.0, Q = 0.0;
#pragma unroll
        for (int i = 0; i < 8; i++) { S += sh[i]; Q += sh[8 + i]; }
        g_csum[off + bc] = S; g_csq[off + bc] = Q;
    }
}

/* ------------ convN64: GN + SiLU + (64->64), 2 og x 2 pts ------------ */
#define CONVN64_SMEM (64*128*4 + 64*32*8 + (64+64+64)*4)
__global__ void __launch_bounds__(128) k_convN64(const float* __restrict__ w,
                                                 const float* __restrict__ bb,
                                                 const float* __restrict__ gamma,
                                                 const float* __restrict__ beta,
                                                 int off, double inv_cnt) {
    extern __shared__ float sm[];
    float* xs = sm;                        /* [64][128] */
    ull*   wp = (ull*)(sm + 64*128);       /* [64][32] */
    float* bs = (float*)(wp + 64*32);
    float* al = bs + 64;
    float* bt = al + 64;
    int tid = threadIdx.x;
    int b = blockIdx.x >> 9;
    int pbase = (blockIdx.x & 511)*128;
    int p = pbase + tid;

    for (int k2 = tid; k2 < 64*32; k2 += 128) {
        int i = k2 >> 5, o2 = k2 & 31;
        wp[k2] = pk2(w[(2*o2)*64 + i], w[(2*o2+1)*64 + i]);
    }
    if (tid < 64) bs[tid] = bb[tid];
    if (tid < 64) {
        int g = tid >> 3;
        double ms = 0.0, qs = 0.0;
#pragma unroll
        for (int cc = 0; cc < 8; cc++) {
            ms += g_csum[off + b*64 + g*8 + cc];
            qs += g_csq [off + b*64 + g*8 + cc];
        }
        double mu  = ms * inv_cnt;
        double var = qs * inv_cnt - mu*mu;
        float rstd = (float)rsqrt(var + 1e-5);
        float a = gamma[tid] * rstd;
        al[tid] = a;
        bt[tid] = beta[tid] - (float)mu * a;
    }
    __syncthreads();

#pragma unroll 1
    for (int ci = 0; ci < 64; ci++) {
        float v  = g_bufA[((size_t)b*64 + ci)*PTS + p];
        float xn = fmaf(v, al[ci], bt[ci]);
        float sg = __fdividef(1.0f, 1.0f + __expf(-xn));
        xs[ci*128 + tid] = xn * sg;
    }
    __syncthreads();

    int og  = tid >> 6;
    int pt0 = (tid & 63) * 2;
    ull acc0[16], acc1[16];
#pragma unroll
    for (int q = 0; q < 16; q++) {
        ull bv = pk2(bs[og*32 + 2*q], bs[og*32 + 2*q + 1]);
        acc0[q] = bv; acc1[q] = bv;
    }
#pragma unroll 2
    for (int i = 0; i < 64; i++) {
        ull xv = *(const ull*)(xs + i*128 + pt0);
        float x0, x1; upk2(xv, x0, x1);
        ull xx0 = pk2(x0, x0), xx1 = pk2(x1, x1);
        const ulonglong2* wr = (const ulonglong2*)(wp + i*32 + og*16);
#pragma unroll
        for (int q = 0; q < 8; q++) {
            ulonglong2 wq = wr[q];
            acc0[2*q]   = fma2(wq.x, xx0, acc0[2*q]);
            acc1[2*q]   = fma2(wq.x, xx1, acc1[2*q]);
            acc0[2*q+1] = fma2(wq.y, xx0, acc0[2*q+1]);
            acc1[2*q+1] = fma2(wq.y, xx1, acc1[2*q+1]);
        }
    }
    float* yb = g_bufB + ((size_t)b*64)*PTS + pbase + pt0;
#pragma unroll
    for (int q = 0; q < 16; q++) {
        int o = og*32 + 2*q;
        float a00, a01, a10, a11;
        upk2(acc0[q], a00, a01);
        upk2(acc1[q], a10, a11);
        *(float2*)(yb + (size_t)o*PTS)     = make_float2(a00, a10);
        *(float2*)(yb + (size_t)(o+1)*PTS) = make_float2(a01, a11);
    }
}

/* ------------ conv128: GN + SiLU + (64->128), 256 thr, 4 og x 2 pts ------------ */
#define CONV128_SMEM (64*128*4 + 64*64*8 + (128+64+64)*4)
__global__ void __launch_bounds__(256) k_conv128(const float* __restrict__ w,
                                                 const float* __restrict__ bb,
                                                 const float* __restrict__ gamma,
                                                 const float* __restrict__ beta,
                                                 int off, double inv_cnt) {
    extern __shared__ float sm[];
    float* xs = sm;                        /* [64][128] */
    ull*   wp = (ull*)(sm + 64*128);       /* [64][64] out-pairs */
    float* bs = (float*)(wp + 64*64);      /* [128] */
    float* al = bs + 128;
    float* bt = al + 64;
    int tid = threadIdx.x;
    int b = blockIdx.x >> 9;
    int pbase = (blockIdx.x & 511)*128;

    for (int k2 = tid; k2 < 64*64; k2 += 256) {
        int i = k2 >> 6, o2 = k2 & 63;
        wp[k2] = pk2(w[(2*o2)*64 + i], w[(2*o2+1)*64 + i]);
    }
    if (tid < 128) bs[tid] = bb[tid];
    if (tid < 64) {
        int g = tid >> 3;
        double ms = 0.0, qs = 0.0;
#pragma unroll
        for (int cc = 0; cc < 8; cc++) {
            ms += g_csum[off + b*64 + g*8 + cc];
            qs += g_csq [off + b*64 + g*8 + cc];
        }
        double mu  = ms * inv_cnt;
        double var = qs * inv_cnt - mu*mu;
        float rstd = (float)rsqrt(var + 1e-5);
        float a = gamma[tid] * rstd;
        al[tid] = a;
        bt[tid] = beta[tid] - (float)mu * a;
    }
    __syncthreads();

    {
        int h = tid >> 7, pt = tid & 127;
        int p = pbase + pt;
#pragma unroll 1
        for (int cc = 0; cc < 32; cc++) {
            int ci = h*32 + cc;
            float v  = g_bufB[((size_t)b*64 + ci)*PTS + p];
            float xn = fmaf(v, al[ci], bt[ci]);
            float sg = __fdividef(1.0f, 1.0f + __expf(-xn));
            xs[ci*128 + pt] = xn * sg;
        }
    }
    __syncthreads();

    int og  = tid >> 6;            /* 0..3 */
    int pt0 = (tid & 63) * 2;
    ull acc0[16], acc1[16];
#pragma unroll
    for (int q = 0; q < 16; q++) {
        ull bv = pk2(bs[og*32 + 2*q], bs[og*32 + 2*q + 1]);
        acc0[q] = bv; acc1[q] = bv;
    }
#pragma unroll 2
    for (int i = 0; i < 64; i++) {
        ull xv = *(const ull*)(xs + i*128 + pt0);
        float x0, x1; upk2(xv, x0, x1);
        ull xx0 = pk2(x0, x0), xx1 = pk2(x1, x1);
        const ulonglong2* wr = (const ulonglong2*)(wp + i*64 + og*16);
#pragma unroll
        for (int q = 0; q < 8; q++) {
            ulonglong2 wq = wr[q];
            acc0[2*q]   = fma2(wq.x, xx0, acc0[2*q]);
            acc1[2*q]   = fma2(wq.x, xx1, acc1[2*q]);
            acc0[2*q+1] = fma2(wq.y, xx0, acc0[2*q+1]);
            acc1[2*q+1] = fma2(wq.y, xx1, acc1[2*q+1]);
        }
    }
    float* yb = g_bufA + ((size_t)b*128)*PTS + pbase + pt0;
#pragma unroll
    for (int q = 0; q < 16; q++) {
        int o = og*32 + 2*q;
        float a00, a01, a10, a11;
        upk2(acc0[q], a00, a01);
        upk2(acc1[q], a10, a11);
        *(float2*)(yb + (size_t)o*PTS)     = make_float2(a00, a10);
        *(float2*)(yb + (size_t)(o+1)*PTS) = make_float2(a01, a11);
    }
}

/* ------------ final: GN + SiLU + max over K ------------ */
__global__ void __launch_bounds__(256) k_final(const float* __restrict__ gamma,
                                               const float* __restrict__ beta,
                                               float* __restrict__ out,
                                               int off, double inv_cnt) {
    int blk = blockIdx.x;
    int bc = blk >> 5;
    int chunk = blk & 31;
    int b = bc >> 7, c = bc & 127;
    __shared__ float s_a, s_b;
    if (threadIdx.x == 0) {
        int g = c >> 4;
        double ms = 0.0, qs = 0.0;
#pragma unroll
        for (int cc = 0; cc < 16; cc++) {
            ms += g_csum[off + b*128 + g*16 + cc];
            qs += g_csq [off + b*128 + g*16 + cc];
        }
        double mu  = ms * inv_cnt;
        double var = qs * inv_cnt - mu*mu;
        float rstd = (float)rsqrt(var + 1e-5);
        float a = gamma[c] * rstd;
        s_a = a;
        s_b = beta[c] - (float)mu * a;
    }
    __syncthreads();
    float a = s_a, bt = s_b;
    int w = threadIdx.x >> 5, lane = threadIdx.x & 31;
    const float* base = g_bufA + (size_t)bc*PTS;
#pragma unroll 1
    for (int j = 0; j < 8; j++) {
        int s = chunk*64 + w*8 + j;
        float v  = base[s*32 + lane];
        float xn = fmaf(v, a, bt);
        float sg = __fdividef(1.0f, 1.0f + __expf(-xn));
        float val = xn * sg;
#pragma unroll
        for (int o = 16; o; o >>= 1)
            val = fmaxf(val, __shfl_xor_sync(0xffffffffu, val, o));
        if (lane == 0) out[(size_t)bc*S_ + s] = val;
    }
}

extern "C" void kernel_launch(void* const* d_in, const int* in_sizes, int n_in,
                              void* d_out, int out_size) {
    const float* coords   = (const float*)d_in[0];
    const float* features = (const float*)d_in[1];
    const float* w0 = (const float*)d_in[2];
    const float* b0 = (const float*)d_in[3];
    const float* g0 = (const float*)d_in[4];
    const float* be0= (const float*)d_in[5];
    const float* w1 = (const float*)d_in[6];
    const float* b1 = (const float*)d_in[7];
    const float* g1 = (const float*)d_in[8];
    const float* be1= (const float*)d_in[9];
    const float* w2 = (const float*)d_in[10];
    const float* b2 = (const float*)d_in[11];
    const float* g2 = (const float*)d_in[12];
    const float* be2= (const float*)d_in[13];
    float* out = (float*)d_out;

    cudaFuncSetAttribute(k_fused,   cudaFuncAttributeMaxDynamicSharedMemorySize, FUSED_SMEM);
    cudaFuncSetAttribute(k_convN64, cudaFuncAttributeMaxDynamicSharedMemorySize, CONVN64_SMEM);
    cudaFuncSetAttribute(k_conv128, cudaFuncAttributeMaxDynamicSharedMemorySize, CONV128_SMEM);

    dim3 tg(N_/32, C_/32, B_);
    k_transpose<<<tg, dim3(32,8)>>>(features);
    /* 8 FPS producers + 1024 ball/conv0 consumers */
    k_fused<<<8 + B_*128, 512, FUSED_SMEM>>>(coords, w0, b0);
    k_stats<64,true><<<B_*64, 256>>>(0);
    k_convN64<<<B_*512, 128, CONVN64_SMEM>>>(w1, b1, g0, be0, 0, 1.0/(8.0*PTS));
    k_stats<64,false><<<B_*64, 256>>>(512);
    k_conv128<<<B_*512, 256, CONV128_SMEM>>>(w2, b2, g1, be1, 512, 1.0/(8.0*PTS));
    k_stats<128,true><<<B_*128, 256>>>(1024);
    k_final<<<B_*128*32, 256>>>(g2, be2, out, 1024, 1.0/(16.0*PTS));
}

// round 14
// speedup vs baseline: 1.2128x; 1.1231x over previous
#include <cuda_runtime.h>
#include <math.h>
#include <stdint.h>

#define B_  8
#define N_  8192
#define C_  64
#define S_  2048
#define KNB 32
#define PTS (S_*KNB)
typedef unsigned long long ull;

__device__ float    g_featT[(size_t)B_*N_*C_];
__device__ float    g_centers[B_*3*S_];
__device__ float    g_bufA[(size_t)B_*128*PTS];
__device__ float    g_bufB[(size_t)B_*128*PTS];
__device__ double   g_csum[2048];
__device__ double   g_csq [2048];
__device__ unsigned g_prog[8];

__device__ __forceinline__ ull pk2(float lo, float hi) {
    ull r; asm("mov.b64 %0,{%1,%2};" : "=l"(r) : "f"(lo), "f"(hi)); return r;
}
__device__ __forceinline__ void upk2(ull v, float& lo, float& hi) {
    asm("mov.b64 {%0,%1},%2;" : "=f"(lo), "=f"(hi) : "l"(v));
}
__device__ __forceinline__ ull add2(ull a, ull b) {
    ull r; asm("add.rn.f32x2 %0,%1,%2;" : "=l"(r) : "l"(a), "l"(b)); return r;
}
__device__ __forceinline__ ull mul2(ull a, ull b) {
    ull r; asm("mul.rn.f32x2 %0,%1,%2;" : "=l"(r) : "l"(a), "l"(b)); return r;
}
__device__ __forceinline__ ull fma2(ull a, ull b, ull c) {
    ull r; asm("fma.rn.f32x2 %0,%1,%2,%3;" : "=l"(r) : "l"(a), "l"(b), "l"(c)); return r;
}

/* ------------ transpose features [b][c][n] -> [b][n][c] ------------ */
__global__ void k_transpose(const float* __restrict__ f) {
    __shared__ float t[32][33];
    int b = blockIdx.z;
    int nb = blockIdx.x * 32, cb = blockIdx.y * 32;
    int tx = threadIdx.x, ty = threadIdx.y;
#pragma unroll
    for (int j = 0; j < 32; j += 8)
        t[ty + j][tx] = f[((size_t)b*C_ + cb + ty + j)*N_ + nb + tx];
    __syncthreads();
#pragma unroll
    for (int j = 0; j < 32; j += 8)
        g_featT[((size_t)b*N_ + nb + ty + j)*C_ + cb + tx] = t[tx][ty + j];
}

/* ------------ fused: FPS (blocks 0-7) + ball/conv0 workers (blocks 8+) ------------ */
#define FUSED_SMEM (3*N_*4 + 64*4)
__global__ void __launch_bounds__(512, 1) k_fused(const float* __restrict__ coords,
                                                  const float* __restrict__ w0,
                                                  const float* __restrict__ b0) {
    extern __shared__ float sm[];
    int tid = threadIdx.x;
    int lane = tid & 31, wid = tid >> 5;

    if (blockIdx.x < 8) {
        /* ================= FPS producer ================= */
        float* sx = sm; float* sy = sm + N_; float* sz = sm + 2*N_;
        unsigned* wbv = (unsigned*)(sm + 3*N_);
        unsigned* wbn = wbv + 32;
        int b = blockIdx.x;
        const float* cb = coords + (size_t)b*3*N_;

        ull pxp[8], pyp[8], pzp[8];
        float mind[16];
#pragma unroll
        for (int jj = 0; jj < 8; jj++) {
            int n0 = (2*jj)*512 + tid, n1 = n0 + 512;
            float x0 = cb[n0],        x1 = cb[n1];
            float y0 = cb[N_ + n0],   y1 = cb[N_ + n1];
            float z0 = cb[2*N_ + n0], z1 = cb[2*N_ + n1];
            sx[n0] = x0; sx[n1] = x1;
            sy[n0] = y0; sy[n1] = y1;
            sz[n0] = z0; sz[n1] = z1;
            pxp[jj] = pk2(x0, x1); pyp[jj] = pk2(y0, y1); pzp[jj] = pk2(z0, z1);
            mind[2*jj] = 1e10f; mind[2*jj+1] = 1e10f;
        }
        float lx = cb[0], ly = cb[N_], lz = cb[2*N_];
        if (tid == 0) {
            g_centers[(b*3+0)*S_] = lx;
            g_centers[(b*3+1)*S_] = ly;
            g_centers[(b*3+2)*S_] = lz;
        }
        __syncthreads();

        for (int step = 1; step < S_; ++step) {
            ull nlx = pk2(-lx, -lx), nly = pk2(-ly, -ly), nlz = pk2(-lz, -lz);
            float bd = -1.0f;
#pragma unroll
            for (int jj = 0; jj < 8; jj++) {
                ull dx = add2(pxp[jj], nlx);
                ull dy = add2(pyp[jj], nly);
                ull dz = add2(pzp[jj], nlz);
                ull s  = mul2(dx, dx);
                ull t  = mul2(dy, dy);
                s = add2(s, t);
                t = mul2(dz, dz);
                s = add2(s, t);
                float d0, d1; upk2(s, d0, d1);
                float m0 = fminf(mind[2*jj],   d0); mind[2*jj]   = m0;
                float m1 = fminf(mind[2*jj+1], d1); mind[2*jj+1] = m1;
                bd = fmaxf(bd, m0);
                bd = fmaxf(bd, m1);
            }
            unsigned bdb = __float_as_uint(bd);
            unsigned wv  = __reduce_max_sync(0xffffffffu, bdb);
            unsigned cand = 0xffffffffu;
            if (bdb == wv) {
#pragma unroll
                for (int j = 15; j >= 0; j--)
                    if (__float_as_uint(mind[j]) == wv)
                        cand = (unsigned)(j*512 + tid);
            }
            unsigned wn = __reduce_min_sync(0xffffffffu, cand);
            int pb = (step & 1) * 16;
            if (lane == 0) { wbv[pb + wid] = wv; wbn[pb + wid] = wn; }
            __syncthreads();
            unsigned v  = wbv[pb + (lane & 15)];
            unsigned nn = wbn[pb + (lane & 15)];
            unsigned vm = __reduce_max_sync(0xffffffffu, v);
            unsigned c2 = (v == vm) ? nn : 0xffffffffu;
            unsigned win = __reduce_min_sync(0xffffffffu, c2);
            lx = sx[win]; ly = sy[win]; lz = sz[win];
            if (tid == 0) {
                g_centers[(b*3+0)*S_ + step] = lx;
                g_centers[(b*3+1)*S_ + step] = ly;
                g_centers[(b*3+2)*S_ + step] = lz;
                if ((step & 15) == 15) {
                    unsigned pv = (unsigned)(step + 1);
                    asm volatile("st.release.gpu.u32 [%0], %1;"
                                 :: "l"(g_prog + b), "r"(pv) : "memory");
                }
            }
        }
    } else {
        /* ================= ball + conv0 consumer ================= */
        int w = blockIdx.x - 8;
        int b = w & 7;
        int cbase = (w >> 3) * 16;
        float* xs = sm;                     /* [68][256] */
        ull*   wp = (ull*)(sm + 68*256);    /* [68][32] */
        float* bs = (float*)(wp + 68*32);   /* [64] */
        float* cs = bs + 64;                /* [3][16] */
        int*   ns = (int*)(cs + 48);        /* [16][32] */
        const float* cb = coords + (size_t)b*3*N_;

        for (int k2 = tid; k2 < 68*32; k2 += 512) {
            int i = k2 >> 5, o2 = k2 & 31;
            float a = (i < 67) ? w0[(2*o2)*67 + i]   : 0.0f;
            float c = (i < 67) ? w0[(2*o2+1)*67 + i] : 0.0f;
            wp[k2] = pk2(a, c);
        }
        if (tid < 64) bs[tid] = b0[tid];

        if (tid == 0) {
            unsigned target = (unsigned)(cbase + 16);
            for (;;) {
                unsigned v;
                asm volatile("ld.acquire.gpu.u32 %0, [%1];"
                             : "=r"(v) : "l"(g_prog + b) : "memory");
                if (v >= target) break;
                __nanosleep(1000);
            }
        }
        __syncthreads();
        if (tid < 48) {
            int d = tid >> 4, s = cbase + (tid & 15);
            cs[tid] = g_centers[(b*3 + d)*S_ + s];
        }
        __syncthreads();

        {
            float cx = cs[wid], cy = cs[16 + wid], cz = cs[32 + wid];
            float cn = __fadd_rn(__fadd_rn(__fmul_rn(cx,cx), __fmul_rn(cy,cy)), __fmul_rn(cz,cz));
            int found = 0, firstn = 0;
            int* op = ns + wid*KNB;
            for (int base = 0; base < N_; base += 32) {
                int n = base + lane;
                float x = __ldg(cb + n), y = __ldg(cb + N_ + n), z = __ldg(cb + 2*N_ + n);
                float pn = __fadd_rn(__fadd_rn(__fmul_rn(x,x), __fmul_rn(y,y)), __fmul_rn(z,z));
                float cp = __fadd_rn(__fadd_rn(__fmul_rn(cx,x), __fmul_rn(cy,y)), __fmul_rn(cz,z));
                float d2 = __fsub_rn(__fadd_rn(cn, pn), __fmul_rn(2.0f, cp));
                bool hit = d2 < 0.0625f;
                unsigned bal = __ballot_sync(0xffffffffu, hit);
                if (bal) {
                    if (found == 0) firstn = base + __ffs(bal) - 1;
                    int slot = found + __popc(bal & ((1u << lane) - 1u));
                    if (hit && slot < KNB) op[slot] = n;
                    found += __popc(bal);
                    if (found >= KNB) break;
                }
            }
            if (found < KNB) {
                int fill = (found > 0) ? firstn : 0;
                for (int sl = found + lane; sl < KNB; sl += 32) op[sl] = fill;
            }
        }
        __syncthreads();

        for (int tile = 0; tile < 2; tile++) {
            int pb2 = tile * 256;
            {
                int h = tid >> 8, pt = tid & 255;
                int lp = pb2 + pt;
                int sl = lp >> 5;
                int n = ns[sl*KNB + (lp & 31)];
                const float4* fp = (const float4*)(g_featT + ((size_t)b*N_ + n)*C_);
                if (h == 0) {
                    xs[0*256 + pt] = __fsub_rn(cb[n],        cs[sl]);
                    xs[1*256 + pt] = __fsub_rn(cb[N_ + n],   cs[16 + sl]);
                    xs[2*256 + pt] = __fsub_rn(cb[2*N_ + n], cs[32 + sl]);
#pragma unroll
                    for (int q = 0; q < 8; q++) {
                        float4 v = fp[q]; int ib = 3 + 4*q;
                        xs[(ib+0)*256 + pt] = v.x; xs[(ib+1)*256 + pt] = v.y;
                        xs[(ib+2)*256 + pt] = v.z; xs[(ib+3)*256 + pt] = v.w;
                    }
                } else {
#pragma unroll
                    for (int q = 8; q < 16; q++) {
                        float4 v = fp[q]; int ib = 3 + 4*q;
                        xs[(ib+0)*256 + pt] = v.x; xs[(ib+1)*256 + pt] = v.y;
                        xs[(ib+2)*256 + pt] = v.z; xs[(ib+3)*256 + pt] = v.w;
                    }
                    xs[67*256 + pt] = 0.0f;
                }
            }
            __syncthreads();

            int og  = tid >> 7;
            int pr  = tid & 127;
            int pt0 = pr * 2;
            ull acc0[8], acc1[8];
#pragma unroll
            for (int q = 0; q < 8; q++) {
                ull bv = pk2(bs[og*16 + 2*q], bs[og*16 + 2*q + 1]);
                acc0[q] = bv; acc1[q] = bv;
            }
#pragma unroll 2
            for (int i = 0; i < 68; i++) {
                ull xv = *(const ull*)(xs + i*256 + pt0);
                float x0, x1; upk2(xv, x0, x1);
                ull xx0 = pk2(x0, x0), xx1 = pk2(x1, x1);
                const ulonglong2* wr = (const ulonglong2*)(wp + i*32 + og*8);
#pragma unroll
                for (int q2 = 0; q2 < 4; q2++) {
                    ulonglong2 wq = wr[q2];
                    acc0[2*q2]   = fma2(wq.x, xx0, acc0[2*q2]);
                    acc1[2*q2]   = fma2(wq.x, xx1, acc1[2*q2]);
                    acc0[2*q2+1] = fma2(wq.y, xx0, acc0[2*q2+1]);
                    acc1[2*q2+1] = fma2(wq.y, xx1, acc1[2*q2+1]);
                }
            }
            float* yb = g_bufA + ((size_t)b*64)*PTS + cbase*KNB + pb2 + pt0;
#pragma unroll
            for (int q = 0; q < 8; q++) {
                int o = og*16 + 2*q;
                float a00, a01, a10, a11;
                upk2(acc0[q], a00, a01);
                upk2(acc1[q], a10, a11);
                *(float2*)(yb + (size_t)o*PTS)     = make_float2(a00, a10);
                *(float2*)(yb + (size_t)(o+1)*PTS) = make_float2(a01, a11);
            }
            __syncthreads();
        }
    }
}

/* ------------ per-(b,c) stats: deterministic two-stage ------------ */
template<int COUT, bool SRC_A>
__global__ void __launch_bounds__(256) k_stats(int off) {
    const float* y = SRC_A ? g_bufA : g_bufB;
    int bc = blockIdx.x;
    const float4* p4 = (const float4*)(y + (size_t)bc*PTS);
    float s = 0.0f, q = 0.0f;
    for (int i = threadIdx.x; i < PTS/4; i += 256) {
        float4 v = p4[i];
        s += v.x + v.y + v.z + v.w;
        q += v.x*v.x + v.y*v.y + v.z*v.z + v.w*v.w;
    }
    double ds = (double)s, dq = (double)q;
    int lane = threadIdx.x & 31, w = threadIdx.x >> 5;
#pragma unroll
    for (int o = 16; o; o >>= 1) {
        ds += __shfl_xor_sync(0xffffffffu, ds, o);
        dq += __shfl_xor_sync(0xffffffffu, dq, o);
    }
    __shared__ double sh[16];
    if (lane == 0) { sh[w] = ds; sh[8 + w] = dq; }
    __syncthreads();
    if (threadIdx.x == 0) {
        double S = 0.0, Q = 0.0;
#pragma unroll
        for (int i = 0; i < 8; i++) { S += sh[i]; Q += sh[8 + i]; }
        g_csum[off + bc] = S; g_csq[off + bc] = Q;
    }
}

/* ------------ convN64: GN + SiLU + (64->64), 2 og x 2 pts ------------ */
#define CONVN64_SMEM (64*128*4 + 64*32*8 + (64+64+64)*4)
__global__ void __launch_bounds__(128) k_convN64(const float* __restrict__ w,
                                                 const float* __restrict__ bb,
                                                 const float* __restrict__ gamma,
                                                 const float* __restrict__ beta,
                                                 int off, double inv_cnt) {
    extern __shared__ float sm[];
    float* xs = sm;                        /* [64][128] */
    ull*   wp = (ull*)(sm + 64*128);       /* [64][32] */
    float* bs = (float*)(wp + 64*32);
    float* al = bs + 64;
    float* bt = al + 64;
    int tid = threadIdx.x;
    int b = blockIdx.x >> 9;
    int pbase = (blockIdx.x & 511)*128;
    int p = pbase + tid;

    for (int k2 = tid; k2 < 64*32; k2 += 128) {
        int i = k2 >> 5, o2 = k2 & 31;
        wp[k2] = pk2(w[(2*o2)*64 + i], w[(2*o2+1)*64 + i]);
    }
    if (tid < 64) bs[tid] = bb[tid];
    if (tid < 64) {
        int g = tid >> 3;
        double ms = 0.0, qs = 0.0;
#pragma unroll
        for (int cc = 0; cc < 8; cc++) {
            ms += g_csum[off + b*64 + g*8 + cc];
            qs += g_csq [off + b*64 + g*8 + cc];
        }
        double mu  = ms * inv_cnt;
        double var = qs * inv_cnt - mu*mu;
        float rstd = (float)rsqrt(var + 1e-5);
        float a = gamma[tid] * rstd;
        al[tid] = a;
        bt[tid] = beta[tid] - (float)mu * a;
    }
    __syncthreads();

#pragma unroll 8
    for (int ci = 0; ci < 64; ci++) {
        float v  = g_bufA[((size_t)b*64 + ci)*PTS + p];
        float xn = fmaf(v, al[ci], bt[ci]);
        float sg = __fdividef(1.0f, 1.0f + __expf(-xn));
        xs[ci*128 + tid] = xn * sg;
    }
    __syncthreads();

    int og  = tid >> 6;
    int pt0 = (tid & 63) * 2;
    ull acc0[16], acc1[16];
#pragma unroll
    for (int q = 0; q < 16; q++) {
        ull bv = pk2(bs[og*32 + 2*q], bs[og*32 + 2*q + 1]);
        acc0[q] = bv; acc1[q] = bv;
    }
#pragma unroll 2
    for (int i = 0; i < 64; i++) {
        ull xv = *(const ull*)(xs + i*128 + pt0);
        float x0, x1; upk2(xv, x0, x1);
        ull xx0 = pk2(x0, x0), xx1 = pk2(x1, x1);
        const ulonglong2* wr = (const ulonglong2*)(wp + i*32 + og*16);
#pragma unroll
        for (int q = 0; q < 8; q++) {
            ulonglong2 wq = wr[q];
            acc0[2*q]   = fma2(wq.x, xx0, acc0[2*q]);
            acc1[2*q]   = fma2(wq.x, xx1, acc1[2*q]);
            acc0[2*q+1] = fma2(wq.y, xx0, acc0[2*q+1]);
            acc1[2*q+1] = fma2(wq.y, xx1, acc1[2*q+1]);
        }
    }
    float* yb = g_bufB + ((size_t)b*64)*PTS + pbase + pt0;
#pragma unroll
    for (int q = 0; q < 16; q++) {
        int o = og*32 + 2*q;
        float a00, a01, a10, a11;
        upk2(acc0[q], a00, a01);
        upk2(acc1[q], a10, a11);
        *(float2*)(yb + (size_t)o*PTS)     = make_float2(a00, a10);
        *(float2*)(yb + (size_t)(o+1)*PTS) = make_float2(a01, a11);
    }
}

/* ------------ conv128: GN + SiLU + (64->128), 256 thr, 4 og x 2 pts ------------ */
#define CONV128_SMEM (64*128*4 + 64*64*8 + (128+64+64)*4)
__global__ void __launch_bounds__(256) k_conv128(const float* __restrict__ w,
                                                 const float* __restrict__ bb,
                                                 const float* __restrict__ gamma,
                                                 const float* __restrict__ beta,
                                                 int off, double inv_cnt) {
    extern __shared__ float sm[];
    float* xs = sm;                        /* [64][128] */
    ull*   wp = (ull*)(sm + 64*128);       /* [64][64] */
    float* bs = (float*)(wp + 64*64);      /* [128] */
    float* al = bs + 128;
    float* bt = al + 64;
    int tid = threadIdx.x;
    int b = blockIdx.x >> 9;
    int pbase = (blockIdx.x & 511)*128;

    for (int k2 = tid; k2 < 64*64; k2 += 256) {
        int i = k2 >> 6, o2 = k2 & 63;
        wp[k2] = pk2(w[(2*o2)*64 + i], w[(2*o2+1)*64 + i]);
    }
    if (tid < 128) bs[tid] = bb[tid];
    if (tid < 64) {
        int g = tid >> 3;
        double ms = 0.0, qs = 0.0;
#pragma unroll
        for (int cc = 0; cc < 8; cc++) {
            ms += g_csum[off + b*64 + g*8 + cc];
            qs += g_csq [off + b*64 + g*8 + cc];
        }
        double mu  = ms * inv_cnt;
        double var = qs * inv_cnt - mu*mu;
        float rstd = (float)rsqrt(var + 1e-5);
        float a = gamma[tid] * rstd;
        al[tid] = a;
        bt[tid] = beta[tid] - (float)mu * a;
    }
    __syncthreads();

    {
        int h = tid >> 7, pt = tid & 127;
        int p = pbase + pt;
#pragma unroll 4
        for (int cc = 0; cc < 32; cc++) {
            int ci = h*32 + cc;
            float v  = g_bufB[((size_t)b*64 + ci)*PTS + p];
            float xn = fmaf(v, al[ci], bt[ci]);
            float sg = __fdividef(1.0f, 1.0f + __expf(-xn));
            xs[ci*128 + pt] = xn * sg;
        }
    }
    __syncthreads();

    int og  = tid >> 6;
    int pt0 = (tid & 63) * 2;
    ull acc0[16], acc1[16];
#pragma unroll
    for (int q = 0; q < 16; q++) {
        ull bv = pk2(bs[og*32 + 2*q], bs[og*32 + 2*q + 1]);
        acc0[q] = bv; acc1[q] = bv;
    }
#pragma unroll 2
    for (int i = 0; i < 64; i++) {
        ull xv = *(const ull*)(xs + i*128 + pt0);
        float x0, x1; upk2(xv, x0, x1);
        ull xx0 = pk2(x0, x0), xx1 = pk2(x1, x1);
        const ulonglong2* wr = (const ulonglong2*)(wp + i*64 + og*16);
#pragma unroll
        for (int q = 0; q < 8; q++) {
            ulonglong2 wq = wr[q];
            acc0[2*q]   = fma2(wq.x, xx0, acc0[2*q]);
            acc1[2*q]   = fma2(wq.x, xx1, acc1[2*q]);
            acc0[2*q+1] = fma2(wq.y, xx0, acc0[2*q+1]);
            acc1[2*q+1] = fma2(wq.y, xx1, acc1[2*q+1]);
        }
    }
    float* yb = g_bufA + ((size_t)b*128)*PTS + pbase + pt0;
#pragma unroll
    for (int q = 0; q < 16; q++) {
        int o = og*32 + 2*q;
        float a00, a01, a10, a11;
        upk2(acc0[q], a00, a01);
        upk2(acc1[q], a10, a11);
        *(float2*)(yb + (size_t)o*PTS)     = make_float2(a00, a10);
        *(float2*)(yb + (size_t)(o+1)*PTS) = make_float2(a01, a11);
    }
}

/* ------------ final: GN + SiLU + max over K ------------ */
__global__ void __launch_bounds__(256) k_final(const float* __restrict__ gamma,
                                               const float* __restrict__ beta,
                                               float* __restrict__ out,
                                               int off, double inv_cnt) {
    int blk = blockIdx.x;
    int bc = blk >> 5;
    int chunk = blk & 31;
    int b = bc >> 7, c = bc & 127;
    __shared__ float s_a, s_b;
    if (threadIdx.x == 0) {
        int g = c >> 4;
        double ms = 0.0, qs = 0.0;
#pragma unroll
        for (int cc = 0; cc < 16; cc++) {
            ms += g_csum[off + b*128 + g*16 + cc];
            qs += g_csq [off + b*128 + g*16 + cc];
        }
        double mu  = ms * inv_cnt;
        double var = qs * inv_cnt - mu*mu;
        float rstd = (float)rsqrt(var + 1e-5);
        float a = gamma[c] * rstd;
        s_a = a;
        s_b = beta[c] - (float)mu * a;
    }
    __syncthreads();
    float a = s_a, bt = s_b;
    int w = threadIdx.x >> 5, lane = threadIdx.x & 31;
    const float* base = g_bufA + (size_t)bc*PTS;
#pragma unroll 1
    for (int j = 0; j < 8; j++) {
        int s = chunk*64 + w*8 + j;
        float v  = base[s*32 + lane];
        float xn = fmaf(v, a, bt);
        float sg = __fdividef(1.0f, 1.0f + __expf(-xn));
        float val = xn * sg;
#pragma unroll
        for (int o = 16; o; o >>= 1)
            val = fmaxf(val, __shfl_xor_sync(0xffffffffu, val, o));
        if (lane == 0) out[(size_t)bc*S_ + s] = val;
    }
}

extern "C" void kernel_launch(void* const* d_in, const int* in_sizes, int n_in,
                              void* d_out, int out_size) {
    const float* coords   = (const float*)d_in[0];
    const float* features = (const float*)d_in[1];
    const float* w0 = (const float*)d_in[2];
    const float* b0 = (const float*)d_in[3];
    const float* g0 = (const float*)d_in[4];
    const float* be0= (const float*)d_in[5];
    const float* w1 = (const float*)d_in[6];
    const float* b1 = (const float*)d_in[7];
    const float* g1 = (const float*)d_in[8];
    const float* be1= (const float*)d_in[9];
    const float* w2 = (const float*)d_in[10];
    const float* b2 = (const float*)d_in[11];
    const float* g2 = (const float*)d_in[12];
    const float* be2= (const float*)d_in[13];
    float* out = (float*)d_out;

    cudaFuncSetAttribute(k_fused,   cudaFuncAttributeMaxDynamicSharedMemorySize, FUSED_SMEM);
    cudaFuncSetAttribute(k_convN64, cudaFuncAttributeMaxDynamicSharedMemorySize, CONVN64_SMEM);
    cudaFuncSetAttribute(k_conv128, cudaFuncAttributeMaxDynamicSharedMemorySize, CONV128_SMEM);

    dim3 tg(N_/32, C_/32, B_);
    k_transpose<<<tg, dim3(32,8)>>>(features);
    k_fused<<<8 + B_*128, 512, FUSED_SMEM>>>(coords, w0, b0);
    k_stats<64,true><<<B_*64, 256>>>(0);
    k_convN64<<<B_*512, 128, CONVN64_SMEM>>>(w1, b1, g0, be0, 0, 1.0/(8.0*PTS));
    k_stats<64,false><<<B_*64, 256>>>(512);
    k_conv128<<<B_*512, 256, CONV128_SMEM>>>(w2, b2, g1, be1, 512, 1.0/(8.0*PTS));
    k_stats<128,true><<<B_*128, 256>>>(1024);
    k_final<<<B_*128*32, 256>>>(g2, be2, out, 1024, 1.0/(16.0*PTS));
}

// round 15
// speedup vs baseline: 1.2359x; 1.0191x over previous
#include <cuda_runtime.h>
#include <math.h>
#include <stdint.h>

#define B_  8
#define N_  8192
#define C_  64
#define S_  2048
#define KNB 32
#define PTS (S_*KNB)
typedef unsigned long long ull;

__device__ float    g_featT[(size_t)B_*N_*C_];
__device__ float    g_centers[B_*3*S_];
__device__ float    g_bufA[(size_t)B_*128*PTS];
__device__ float    g_bufB[(size_t)B_*128*PTS];
__device__ double   g_csum[2048];
__device__ double   g_csq [2048];
__device__ unsigned g_prog[8];

__device__ __forceinline__ ull pk2(float lo, float hi) {
    ull r; asm("mov.b64 %0,{%1,%2};" : "=l"(r) : "f"(lo), "f"(hi)); return r;
}
__device__ __forceinline__ void upk2(ull v, float& lo, float& hi) {
    asm("mov.b64 {%0,%1},%2;" : "=f"(lo), "=f"(hi) : "l"(v));
}
__device__ __forceinline__ ull add2(ull a, ull b) {
    ull r; asm("add.rn.f32x2 %0,%1,%2;" : "=l"(r) : "l"(a), "l"(b)); return r;
}
__device__ __forceinline__ ull mul2(ull a, ull b) {
    ull r; asm("mul.rn.f32x2 %0,%1,%2;" : "=l"(r) : "l"(a), "l"(b)); return r;
}
__device__ __forceinline__ ull fma2(ull a, ull b, ull c) {
    ull r; asm("fma.rn.f32x2 %0,%1,%2,%3;" : "=l"(r) : "l"(a), "l"(b), "l"(c)); return r;
}

/* ------------ transpose features [b][c][n] -> [b][n][c] ------------ */
__global__ void k_transpose(const float* __restrict__ f) {
    __shared__ float t[32][33];
    int b = blockIdx.z;
    int nb = blockIdx.x * 32, cb = blockIdx.y * 32;
    int tx = threadIdx.x, ty = threadIdx.y;
#pragma unroll
    for (int j = 0; j < 32; j += 8)
        t[ty + j][tx] = f[((size_t)b*C_ + cb + ty + j)*N_ + nb + tx];
    __syncthreads();
#pragma unroll
    for (int j = 0; j < 32; j += 8)
        g_featT[((size_t)b*N_ + nb + ty + j)*C_ + cb + tx] = t[tx][ty + j];
}

/* ------------ fused: FPS (blocks 0-7) + ball/conv0 workers (blocks 8+) ------------ */
#define FUSED_SMEM (3*N_*4 + 64*4)
__global__ void __launch_bounds__(512, 1) k_fused(const float* __restrict__ coords,
                                                  const float* __restrict__ w0,
                                                  const float* __restrict__ b0) {
    extern __shared__ float sm[];
    int tid = threadIdx.x;
    int lane = tid & 31, wid = tid >> 5;

    if (blockIdx.x < 8) {
        /* ================= FPS producer ================= */
        float* sx = sm; float* sy = sm + N_; float* sz = sm + 2*N_;
        unsigned* wbv = (unsigned*)(sm + 3*N_);
        unsigned* wbn = wbv + 32;
        int b = blockIdx.x;
        const float* cb = coords + (size_t)b*3*N_;

        ull pxp[8], pyp[8], pzp[8];
        float mind[16];
#pragma unroll
        for (int jj = 0; jj < 8; jj++) {
            int n0 = (2*jj)*512 + tid, n1 = n0 + 512;
            float x0 = cb[n0],        x1 = cb[n1];
            float y0 = cb[N_ + n0],   y1 = cb[N_ + n1];
            float z0 = cb[2*N_ + n0], z1 = cb[2*N_ + n1];
            sx[n0] = x0; sx[n1] = x1;
            sy[n0] = y0; sy[n1] = y1;
            sz[n0] = z0; sz[n1] = z1;
            pxp[jj] = pk2(x0, x1); pyp[jj] = pk2(y0, y1); pzp[jj] = pk2(z0, z1);
            mind[2*jj] = 1e10f; mind[2*jj+1] = 1e10f;
        }
        float lx = cb[0], ly = cb[N_], lz = cb[2*N_];
        if (tid == 0) {
            g_centers[(b*3+0)*S_] = lx;
            g_centers[(b*3+1)*S_] = ly;
            g_centers[(b*3+2)*S_] = lz;
        }
        __syncthreads();

        for (int step = 1; step < S_; ++step) {
            ull nlx = pk2(-lx, -lx), nly = pk2(-ly, -ly), nlz = pk2(-lz, -lz);
            float bd = -1.0f;
#pragma unroll
            for (int jj = 0; jj < 8; jj++) {
                ull dx = add2(pxp[jj], nlx);
                ull dy = add2(pyp[jj], nly);
                ull dz = add2(pzp[jj], nlz);
                ull s  = mul2(dx, dx);
                ull t  = mul2(dy, dy);
                s = add2(s, t);
                t = mul2(dz, dz);
                s = add2(s, t);
                float d0, d1; upk2(s, d0, d1);
                float m0 = fminf(mind[2*jj],   d0); mind[2*jj]   = m0;
                float m1 = fminf(mind[2*jj+1], d1); mind[2*jj+1] = m1;
                bd = fmaxf(bd, m0);
                bd = fmaxf(bd, m1);
            }
            unsigned bdb = __float_as_uint(bd);
            unsigned wv  = __reduce_max_sync(0xffffffffu, bdb);
            unsigned cand = 0xffffffffu;
            if (bdb == wv) {
#pragma unroll
                for (int j = 15; j >= 0; j--)
                    if (__float_as_uint(mind[j]) == wv)
                        cand = (unsigned)(j*512 + tid);
            }
            unsigned wn = __reduce_min_sync(0xffffffffu, cand);
            int pb = (step & 1) * 16;
            if (lane == 0) { wbv[pb + wid] = wv; wbn[pb + wid] = wn; }
            __syncthreads();
            unsigned v  = wbv[pb + (lane & 15)];
            unsigned nn = wbn[pb + (lane & 15)];
            unsigned vm = __reduce_max_sync(0xffffffffu, v);
            unsigned c2 = (v == vm) ? nn : 0xffffffffu;
            unsigned win = __reduce_min_sync(0xffffffffu, c2);
            lx = sx[win]; ly = sy[win]; lz = sz[win];
            if (tid == 0) {
                g_centers[(b*3+0)*S_ + step] = lx;
                g_centers[(b*3+1)*S_ + step] = ly;
                g_centers[(b*3+2)*S_ + step] = lz;
                if ((step & 15) == 15) {
                    unsigned pv = (unsigned)(step + 1);
                    asm volatile("st.release.gpu.u32 [%0], %1;"
                                 :: "l"(g_prog + b), "r"(pv) : "memory");
                }
            }
        }
    } else {
        /* ================= ball + conv0 consumer ================= */
        int w = blockIdx.x - 8;
        int b = w & 7;
        int cbase = (w >> 3) * 16;
        float* xs = sm;                     /* [68][256] */
        ull*   wp = (ull*)(sm + 68*256);    /* [68][32] */
        float* bs = (float*)(wp + 68*32);   /* [64] */
        float* cs = bs + 64;                /* [3][16] */
        int*   ns = (int*)(cs + 48);        /* [16][32] */
        const float* cb = coords + (size_t)b*3*N_;

        for (int k2 = tid; k2 < 68*32; k2 += 512) {
            int i = k2 >> 5, o2 = k2 & 31;
            float a = (i < 67) ? w0[(2*o2)*67 + i]   : 0.0f;
            float c = (i < 67) ? w0[(2*o2+1)*67 + i] : 0.0f;
            wp[k2] = pk2(a, c);
        }
        if (tid < 64) bs[tid] = b0[tid];

        if (tid == 0) {
            unsigned target = (unsigned)(cbase + 16);
            for (;;) {
                unsigned v;
                asm volatile("ld.acquire.gpu.u32 %0, [%1];"
                             : "=r"(v) : "l"(g_prog + b) : "memory");
                if (v >= target) break;
                __nanosleep(1000);
            }
        }
        __syncthreads();
        if (tid < 48) {
            int d = tid >> 4, s = cbase + (tid & 15);
            cs[tid] = g_centers[(b*3 + d)*S_ + s];
        }
        __syncthreads();

        {
            float cx = cs[wid], cy = cs[16 + wid], cz = cs[32 + wid];
            float cn = __fadd_rn(__fadd_rn(__fmul_rn(cx,cx), __fmul_rn(cy,cy)), __fmul_rn(cz,cz));
            int found = 0, firstn = 0;
            int* op = ns + wid*KNB;
            for (int base = 0; base < N_; base += 32) {
                int n = base + lane;
                float x = __ldg(cb + n), y = __ldg(cb + N_ + n), z = __ldg(cb + 2*N_ + n);
                float pn = __fadd_rn(__fadd_rn(__fmul_rn(x,x), __fmul_rn(y,y)), __fmul_rn(z,z));
                float cp = __fadd_rn(__fadd_rn(__fmul_rn(cx,x), __fmul_rn(cy,y)), __fmul_rn(cz,z));
                float d2 = __fsub_rn(__fadd_rn(cn, pn), __fmul_rn(2.0f, cp));
                bool hit = d2 < 0.0625f;
                unsigned bal = __ballot_sync(0xffffffffu, hit);
                if (bal) {
                    if (found == 0) firstn = base + __ffs(bal) - 1;
                    int slot = found + __popc(bal & ((1u << lane) - 1u));
                    if (hit && slot < KNB) op[slot] = n;
                    found += __popc(bal);
                    if (found >= KNB) break;
                }
            }
            if (found < KNB) {
                int fill = (found > 0) ? firstn : 0;
                for (int sl = found + lane; sl < KNB; sl += 32) op[sl] = fill;
            }
        }
        __syncthreads();

        for (int tile = 0; tile < 2; tile++) {
            int pb2 = tile * 256;
            {
                int h = tid >> 8, pt = tid & 255;
                int lp = pb2 + pt;
                int sl = lp >> 5;
                int n = ns[sl*KNB + (lp & 31)];
                const float4* fp = (const float4*)(g_featT + ((size_t)b*N_ + n)*C_);
                if (h == 0) {
                    xs[0*256 + pt] = __fsub_rn(cb[n],        cs[sl]);
                    xs[1*256 + pt] = __fsub_rn(cb[N_ + n],   cs[16 + sl]);
                    xs[2*256 + pt] = __fsub_rn(cb[2*N_ + n], cs[32 + sl]);
#pragma unroll
                    for (int q = 0; q < 8; q++) {
                        float4 v = fp[q]; int ib = 3 + 4*q;
                        xs[(ib+0)*256 + pt] = v.x; xs[(ib+1)*256 + pt] = v.y;
                        xs[(ib+2)*256 + pt] = v.z; xs[(ib+3)*256 + pt] = v.w;
                    }
                } else {
#pragma unroll
                    for (int q = 8; q < 16; q++) {
                        float4 v = fp[q]; int ib = 3 + 4*q;
                        xs[(ib+0)*256 + pt] = v.x; xs[(ib+1)*256 + pt] = v.y;
                        xs[(ib+2)*256 + pt] = v.z; xs[(ib+3)*256 + pt] = v.w;
                    }
                    xs[67*256 + pt] = 0.0f;
                }
            }
            __syncthreads();

            int og  = tid >> 7;
            int pr  = tid & 127;
            int pt0 = pr * 2;
            ull acc0[8], acc1[8];
#pragma unroll
            for (int q = 0; q < 8; q++) {
                ull bv = pk2(bs[og*16 + 2*q], bs[og*16 + 2*q + 1]);
                acc0[q] = bv; acc1[q] = bv;
            }
#pragma unroll 2
            for (int i = 0; i < 68; i++) {
                ull xv = *(const ull*)(xs + i*256 + pt0);
                float x0, x1; upk2(xv, x0, x1);
                ull xx0 = pk2(x0, x0), xx1 = pk2(x1, x1);
                const ulonglong2* wr = (const ulonglong2*)(wp + i*32 + og*8);
#pragma unroll
                for (int q2 = 0; q2 < 4; q2++) {
                    ulonglong2 wq = wr[q2];
                    acc0[2*q2]   = fma2(wq.x, xx0, acc0[2*q2]);
                    acc1[2*q2]   = fma2(wq.x, xx1, acc1[2*q2]);
                    acc0[2*q2+1] = fma2(wq.y, xx0, acc0[2*q2+1]);
                    acc1[2*q2+1] = fma2(wq.y, xx1, acc1[2*q2+1]);
                }
            }
            float* yb = g_bufA + ((size_t)b*64)*PTS + cbase*KNB + pb2 + pt0;
#pragma unroll
            for (int q = 0; q < 8; q++) {
                int o = og*16 + 2*q;
                float a00, a01, a10, a11;
                upk2(acc0[q], a00, a01);
                upk2(acc1[q], a10, a11);
                *(float2*)(yb + (size_t)o*PTS)     = make_float2(a00, a10);
                *(float2*)(yb + (size_t)(o+1)*PTS) = make_float2(a01, a11);
            }
            __syncthreads();
        }
    }
}

/* ------------ per-(b,c) stats: deterministic two-stage ------------ */
template<int COUT, bool SRC_A>
__global__ void __launch_bounds__(256) k_stats(int off) {
    const float* y = SRC_A ? g_bufA : g_bufB;
    int bc = blockIdx.x;
    const float4* p4 = (const float4*)(y + (size_t)bc*PTS);
    float s = 0.0f, q = 0.0f;
    for (int i = threadIdx.x; i < PTS/4; i += 256) {
        float4 v = p4[i];
        s += v.x + v.y + v.z + v.w;
        q += v.x*v.x + v.y*v.y + v.z*v.z + v.w*v.w;
    }
    double ds = (double)s, dq = (double)q;
    int lane = threadIdx.x & 31, w = threadIdx.x >> 5;
#pragma unroll
    for (int o = 16; o; o >>= 1) {
        ds += __shfl_xor_sync(0xffffffffu, ds, o);
        dq += __shfl_xor_sync(0xffffffffu, dq, o);
    }
    __shared__ double sh[16];
    if (lane == 0) { sh[w] = ds; sh[8 + w] = dq; }
    __syncthreads();
    if (threadIdx.x == 0) {
        double S = 0.0, Q = 0.0;
#pragma unroll
        for (int i = 0; i < 8; i++) { S += sh[i]; Q += sh[8 + i]; }
        g_csum[off + bc] = S; g_csq[off + bc] = Q;
    }
}

/* ------------ convN64: GN + SiLU + (64->64), 256 thr, 4 og x 2 pts ------------ */
#define CONVN64_SMEM (64*128*4 + 64*32*8 + (64+64+64)*4)
__global__ void __launch_bounds__(256) k_convN64(const float* __restrict__ w,
                                                 const float* __restrict__ bb,
                                                 const float* __restrict__ gamma,
                                                 const float* __restrict__ beta,
                                                 int off, double inv_cnt) {
    extern __shared__ float sm[];
    float* xs = sm;                        /* [64][128] */
    ull*   wp = (ull*)(sm + 64*128);       /* [64][32] */
    float* bs = (float*)(wp + 64*32);
    float* al = bs + 64;
    float* bt = al + 64;
    int tid = threadIdx.x;
    int b = blockIdx.x >> 9;
    int pbase = (blockIdx.x & 511)*128;

    for (int k2 = tid; k2 < 64*32; k2 += 256) {
        int i = k2 >> 5, o2 = k2 & 31;
        wp[k2] = pk2(w[(2*o2)*64 + i], w[(2*o2+1)*64 + i]);
    }
    if (tid < 64) bs[tid] = bb[tid];
    if (tid < 64) {
        int g = tid >> 3;
        double ms = 0.0, qs = 0.0;
#pragma unroll
        for (int cc = 0; cc < 8; cc++) {
            ms += g_csum[off + b*64 + g*8 + cc];
            qs += g_csq [off + b*64 + g*8 + cc];
        }
        double mu  = ms * inv_cnt;
        double var = qs * inv_cnt - mu*mu;
        float rstd = (float)rsqrt(var + 1e-5);
        float a = gamma[tid] * rstd;
        al[tid] = a;
        bt[tid] = beta[tid] - (float)mu * a;
    }
    __syncthreads();

    {
        int h = tid >> 7, pt = tid & 127;
        int p = pbase + pt;
#pragma unroll 8
        for (int cc = 0; cc < 32; cc++) {
            int ci = h*32 + cc;
            float v  = g_bufA[((size_t)b*64 + ci)*PTS + p];
            float xn = fmaf(v, al[ci], bt[ci]);
            float sg = __fdividef(1.0f, 1.0f + __expf(-xn));
            xs[ci*128 + pt] = xn * sg;
        }
    }
    __syncthreads();

    int og  = tid >> 6;            /* 0..3: outputs og*16..og*16+15 */
    int pt0 = (tid & 63) * 2;
    ull acc0[8], acc1[8];
#pragma unroll
    for (int q = 0; q < 8; q++) {
        ull bv = pk2(bs[og*16 + 2*q], bs[og*16 + 2*q + 1]);
        acc0[q] = bv; acc1[q] = bv;
    }
#pragma unroll 2
    for (int i = 0; i < 64; i++) {
        ull xv = *(const ull*)(xs + i*128 + pt0);
        float x0, x1; upk2(xv, x0, x1);
        ull xx0 = pk2(x0, x0), xx1 = pk2(x1, x1);
        const ulonglong2* wr = (const ulonglong2*)(wp + i*32 + og*8);
#pragma unroll
        for (int q2 = 0; q2 < 4; q2++) {
            ulonglong2 wq = wr[q2];
            acc0[2*q2]   = fma2(wq.x, xx0, acc0[2*q2]);
            acc1[2*q2]   = fma2(wq.x, xx1, acc1[2*q2]);
            acc0[2*q2+1] = fma2(wq.y, xx0, acc0[2*q2+1]);
            acc1[2*q2+1] = fma2(wq.y, xx1, acc1[2*q2+1]);
        }
    }
    float* yb = g_bufB + ((size_t)b*64)*PTS + pbase + pt0;
#pragma unroll
    for (int q = 0; q < 8; q++) {
        int o = og*16 + 2*q;
        float a00, a01, a10, a11;
        upk2(acc0[q], a00, a01);
        upk2(acc1[q], a10, a11);
        *(float2*)(yb + (size_t)o*PTS)     = make_float2(a00, a10);
        *(float2*)(yb + (size_t)(o+1)*PTS) = make_float2(a01, a11);
    }
}

/* ------------ conv128: GN + SiLU + (64->128), 256 thr, 4 og x 2 pts ------------ */
#define CONV128_SMEM (64*128*4 + 64*64*8 + (128+64+64)*4)
__global__ void __launch_bounds__(256) k_conv128(const float* __restrict__ w,
                                                 const float* __restrict__ bb,
                                                 const float* __restrict__ gamma,
                                                 const float* __restrict__ beta,
                                                 int off, double inv_cnt) {
    extern __shared__ float sm[];
    float* xs = sm;                        /* [64][128] */
    ull*   wp = (ull*)(sm + 64*128);       /* [64][64] */
    float* bs = (float*)(wp + 64*64);      /* [128] */
    float* al = bs + 128;
    float* bt = al + 64;
    int tid = threadIdx.x;
    int b = blockIdx.x >> 9;
    int pbase = (blockIdx.x & 511)*128;

    for (int k2 = tid; k2 < 64*64; k2 += 256) {
        int i = k2 >> 6, o2 = k2 & 63;
        wp[k2] = pk2(w[(2*o2)*64 + i], w[(2*o2+1)*64 + i]);
    }
    if (tid < 128) bs[tid] = bb[tid];
    if (tid < 64) {
        int g = tid >> 3;
        double ms = 0.0, qs = 0.0;
#pragma unroll
        for (int cc = 0; cc < 8; cc++) {
            ms += g_csum[off + b*64 + g*8 + cc];
            qs += g_csq [off + b*64 + g*8 + cc];
        }
        double mu  = ms * inv_cnt;
        double var = qs * inv_cnt - mu*mu;
        float rstd = (float)rsqrt(var + 1e-5);
        float a = gamma[tid] * rstd;
        al[tid] = a;
        bt[tid] = beta[tid] - (float)mu * a;
    }
    __syncthreads();

    {
        int h = tid >> 7, pt = tid & 127;
        int p = pbase + pt;
#pragma unroll 8
        for (int cc = 0; cc < 32; cc++) {
            int ci = h*32 + cc;
            float v  = g_bufB[((size_t)b*64 + ci)*PTS + p];
            float xn = fmaf(v, al[ci], bt[ci]);
            float sg = __fdividef(1.0f, 1.0f + __expf(-xn));
            xs[ci*128 + pt] = xn * sg;
        }
    }
    __syncthreads();

    int og  = tid >> 6;
    int pt0 = (tid & 63) * 2;
    ull acc0[16], acc1[16];
#pragma unroll
    for (int q = 0; q < 16; q++) {
        ull bv = pk2(bs[og*32 + 2*q], bs[og*32 + 2*q + 1]);
        acc0[q] = bv; acc1[q] = bv;
    }
#pragma unroll 2
    for (int i = 0; i < 64; i++) {
        ull xv = *(const ull*)(xs + i*128 + pt0);
        float x0, x1; upk2(xv, x0, x1);
        ull xx0 = pk2(x0, x0), xx1 = pk2(x1, x1);
        const ulonglong2* wr = (const ulonglong2*)(wp + i*64 + og*16);
#pragma unroll
        for (int q = 0; q < 8; q++) {
            ulonglong2 wq = wr[q];
            acc0[2*q]   = fma2(wq.x, xx0, acc0[2*q]);
            acc1[2*q]   = fma2(wq.x, xx1, acc1[2*q]);
            acc0[2*q+1] = fma2(wq.y, xx0, acc0[2*q+1]);
            acc1[2*q+1] = fma2(wq.y, xx1, acc1[2*q+1]);
        }
    }
    float* yb = g_bufA + ((size_t)b*128)*PTS + pbase + pt0;
#pragma unroll
    for (int q = 0; q < 16; q++) {
        int o = og*32 + 2*q;
        float a00, a01, a10, a11;
        upk2(acc0[q], a00, a01);
        upk2(acc1[q], a10, a11);
        *(float2*)(yb + (size_t)o*PTS)     = make_float2(a00, a10);
        *(float2*)(yb + (size_t)(o+1)*PTS) = make_float2(a01, a11);
    }
}

/* ------------ final: GN + SiLU + max over K ------------ */
__global__ void __launch_bounds__(256) k_final(const float* __restrict__ gamma,
                                               const float* __restrict__ beta,
                                               float* __restrict__ out,
                                               int off, double inv_cnt) {
    int blk = blockIdx.x;
    int bc = blk >> 5;
    int chunk = blk & 31;
    int b = bc >> 7, c = bc & 127;
    __shared__ float s_a, s_b;
    if (threadIdx.x == 0) {
        int g = c >> 4;
        double ms = 0.0, qs = 0.0;
#pragma unroll
        for (int cc = 0; cc < 16; cc++) {
            ms += g_csum[off + b*128 + g*16 + cc];
            qs += g_csq [off + b*128 + g*16 + cc];
        }
        double mu  = ms * inv_cnt;
        double var = qs * inv_cnt - mu*mu;
        float rstd = (float)rsqrt(var + 1e-5);
        float a = gamma[c] * rstd;
        s_a = a;
        s_b = beta[c] - (float)mu * a;
    }
    __syncthreads();
    float a = s_a, bt = s_b;
    int w = threadIdx.x >> 5, lane = threadIdx.x & 31;
    const float* base = g_bufA + (size_t)bc*PTS;
#pragma unroll 4
    for (int j = 0; j < 8; j++) {
        int s = chunk*64 + w*8 + j;
        float v  = base[s*32 + lane];
        float xn = fmaf(v, a, bt);
        float sg = __fdividef(1.0f, 1.0f + __expf(-xn));
        float val = xn * sg;
#pragma unroll
        for (int o = 16; o; o >>= 1)
            val = fmaxf(val, __shfl_xor_sync(0xffffffffu, val, o));
        if (lane == 0) out[(size_t)bc*S_ + s] = val;
    }
}

extern "C" void kernel_launch(void* const* d_in, const int* in_sizes, int n_in,
                              void* d_out, int out_size) {
    const float* coords   = (const float*)d_in[0];
    const float* features = (const float*)d_in[1];
    const float* w0 = (const float*)d_in[2];
    const float* b0 = (const float*)d_in[3];
    const float* g0 = (const float*)d_in[4];
    const float* be0= (const float*)d_in[5];
    const float* w1 = (const float*)d_in[6];
    const float* b1 = (const float*)d_in[7];
    const float* g1 = (const float*)d_in[8];
    const float* be1= (const float*)d_in[9];
    const float* w2 = (const float*)d_in[10];
    const float* b2 = (const float*)d_in[11];
    const float* g2 = (const float*)d_in[12];
    const float* be2= (const float*)d_in[13];
    float* out = (float*)d_out;

    cudaFuncSetAttribute(k_fused,   cudaFuncAttributeMaxDynamicSharedMemorySize, FUSED_SMEM);
    cudaFuncSetAttribute(k_convN64, cudaFuncAttributeMaxDynamicSharedMemorySize, CONVN64_SMEM);
    cudaFuncSetAttribute(k_conv128, cudaFuncAttributeMaxDynamicSharedMemorySize, CONV128_SMEM);

    dim3 tg(N_/32, C_/32, B_);
    k_transpose<<<tg, dim3(32,8)>>>(features);
    k_fused<<<8 + B_*128, 512, FUSED_SMEM>>>(coords, w0, b0);
    k_stats<64,true><<<B_*64, 256>>>(0);
    k_convN64<<<B_*512, 256, CONVN64_SMEM>>>(w1, b1, g0, be0, 0, 1.0/(8.0*PTS));
    k_stats<64,false><<<B_*64, 256>>>(512);
    k_conv128<<<B_*512, 256, CONV128_SMEM>>>(w2, b2, g1, be1, 512, 1.0/(8.0*PTS));
    k_stats<128,true><<<B_*128, 256>>>(1024);
    k_final<<<B_*128*32, 256>>>(g2, be2, out, 1024, 1.0/(16.0*PTS));
}

// round 16
// speedup vs baseline: 1.2364x; 1.0004x over previous
#include <cuda_runtime.h>
#include <math.h>
#include <stdint.h>

#define B_  8
#define N_  8192
#define C_  64
#define S_  2048
#define KNB 32
#define PTS (S_*KNB)
typedef unsigned long long ull;

__device__ float    g_featT[(size_t)B_*N_*C_];
__device__ float    g_centers[B_*3*S_];
__device__ float    g_bufA[(size_t)B_*128*PTS];
__device__ float    g_bufB[(size_t)B_*128*PTS];
__device__ double   g_csum[2048];
__device__ double   g_csq [2048];
__device__ unsigned g_prog[8];

__device__ __forceinline__ ull pk2(float lo, float hi) {
    ull r; asm("mov.b64 %0,{%1,%2};" : "=l"(r) : "f"(lo), "f"(hi)); return r;
}
__device__ __forceinline__ void upk2(ull v, float& lo, float& hi) {
    asm("mov.b64 {%0,%1},%2;" : "=f"(lo), "=f"(hi) : "l"(v));
}
__device__ __forceinline__ ull add2(ull a, ull b) {
    ull r; asm("add.rn.f32x2 %0,%1,%2;" : "=l"(r) : "l"(a), "l"(b)); return r;
}
__device__ __forceinline__ ull mul2(ull a, ull b) {
    ull r; asm("mul.rn.f32x2 %0,%1,%2;" : "=l"(r) : "l"(a), "l"(b)); return r;
}
__device__ __forceinline__ ull fma2(ull a, ull b, ull c) {
    ull r; asm("fma.rn.f32x2 %0,%1,%2,%3;" : "=l"(r) : "l"(a), "l"(b), "l"(c)); return r;
}

/* ------------ transpose features [b][c][n] -> [b][n][c] ------------ */
__global__ void k_transpose(const float* __restrict__ f) {
    __shared__ float t[32][33];
    int b = blockIdx.z;
    int nb = blockIdx.x * 32, cb = blockIdx.y * 32;
    int tx = threadIdx.x, ty = threadIdx.y;
#pragma unroll
    for (int j = 0; j < 32; j += 8)
        t[ty + j][tx] = f[((size_t)b*C_ + cb + ty + j)*N_ + nb + tx];
    __syncthreads();
#pragma unroll
    for (int j = 0; j < 32; j += 8)
        g_featT[((size_t)b*N_ + nb + ty + j)*C_ + cb + tx] = t[tx][ty + j];
}

/* ------------ fused: FPS (blocks 0-7) + ball/conv0 workers (blocks 8+) ------------ */
#define FUSED_SMEM (3*N_*4 + 64*4)
__global__ void __launch_bounds__(512, 1) k_fused(const float* __restrict__ coords,
                                                  const float* __restrict__ w0,
                                                  const float* __restrict__ b0) {
    extern __shared__ float sm[];
    int tid = threadIdx.x;
    int lane = tid & 31, wid = tid >> 5;

    if (blockIdx.x < 8) {
        /* ================= FPS producer ================= */
        float* sx = sm; float* sy = sm + N_; float* sz = sm + 2*N_;
        unsigned* wbv = (unsigned*)(sm + 3*N_);
        unsigned* wbn = wbv + 32;
        int b = blockIdx.x;
        const float* cb = coords + (size_t)b*3*N_;

        ull pxp[8], pyp[8], pzp[8];
        float mind[16];
#pragma unroll
        for (int jj = 0; jj < 8; jj++) {
            int n0 = (2*jj)*512 + tid, n1 = n0 + 512;
            float x0 = cb[n0],        x1 = cb[n1];
            float y0 = cb[N_ + n0],   y1 = cb[N_ + n1];
            float z0 = cb[2*N_ + n0], z1 = cb[2*N_ + n1];
            sx[n0] = x0; sx[n1] = x1;
            sy[n0] = y0; sy[n1] = y1;
            sz[n0] = z0; sz[n1] = z1;
            pxp[jj] = pk2(x0, x1); pyp[jj] = pk2(y0, y1); pzp[jj] = pk2(z0, z1);
            mind[2*jj] = 1e10f; mind[2*jj+1] = 1e10f;
        }
        float lx = cb[0], ly = cb[N_], lz = cb[2*N_];
        if (tid == 0) {
            g_centers[(b*3+0)*S_] = lx;
            g_centers[(b*3+1)*S_] = ly;
            g_centers[(b*3+2)*S_] = lz;
        }
        __syncthreads();

        for (int step = 1; step < S_; ++step) {
            ull nlx = pk2(-lx, -lx), nly = pk2(-ly, -ly), nlz = pk2(-lz, -lz);
            float bd = -1.0f;
#pragma unroll
            for (int jj = 0; jj < 8; jj++) {
                ull dx = add2(pxp[jj], nlx);
                ull dy = add2(pyp[jj], nly);
                ull dz = add2(pzp[jj], nlz);
                ull s  = mul2(dx, dx);
                ull t  = mul2(dy, dy);
                s = add2(s, t);
                t = mul2(dz, dz);
                s = add2(s, t);
                float d0, d1; upk2(s, d0, d1);
                float m0 = fminf(mind[2*jj],   d0); mind[2*jj]   = m0;
                float m1 = fminf(mind[2*jj+1], d1); mind[2*jj+1] = m1;
                bd = fmaxf(bd, m0);
                bd = fmaxf(bd, m1);
            }
            unsigned bdb = __float_as_uint(bd);
            unsigned wv  = __reduce_max_sync(0xffffffffu, bdb);
            unsigned cand = 0xffffffffu;
            if (bdb == wv) {
#pragma unroll
                for (int j = 15; j >= 0; j--)
                    if (__float_as_uint(mind[j]) == wv)
                        cand = (unsigned)(j*512 + tid);
            }
            unsigned wn = __reduce_min_sync(0xffffffffu, cand);
            int pb = (step & 1) * 16;
            if (lane == 0) { wbv[pb + wid] = wv; wbn[pb + wid] = wn; }
            __syncthreads();
            unsigned v  = wbv[pb + (lane & 15)];
            unsigned nn = wbn[pb + (lane & 15)];
            unsigned vm = __reduce_max_sync(0xffffffffu, v);
            unsigned c2 = (v == vm) ? nn : 0xffffffffu;
            unsigned win = __reduce_min_sync(0xffffffffu, c2);
            lx = sx[win]; ly = sy[win]; lz = sz[win];
            if (tid == 0) {
                g_centers[(b*3+0)*S_ + step] = lx;
                g_centers[(b*3+1)*S_ + step] = ly;
                g_centers[(b*3+2)*S_ + step] = lz;
                if ((step & 15) == 15) {
                    unsigned pv = (unsigned)(step + 1);
                    asm volatile("st.release.gpu.u32 [%0], %1;"
                                 :: "l"(g_prog + b), "r"(pv) : "memory");
                }
            }
        }
    } else {
        /* ================= ball + conv0 consumer ================= */
        int w = blockIdx.x - 8;
        int b = w & 7;
        int cbase = (w >> 3) * 16;
        float* xs = sm;                     /* [68][256] */
        ull*   wp = (ull*)(sm + 68*256);    /* [68][32] */
        float* bs = (float*)(wp + 68*32);   /* [64] */
        float* cs = bs + 64;                /* [3][16] */
        int*   ns = (int*)(cs + 48);        /* [16][32] */
        const float* cb = coords + (size_t)b*3*N_;

        for (int k2 = tid; k2 < 68*32; k2 += 512) {
            int i = k2 >> 5, o2 = k2 & 31;
            float a = (i < 67) ? w0[(2*o2)*67 + i]   : 0.0f;
            float c = (i < 67) ? w0[(2*o2+1)*67 + i] : 0.0f;
            wp[k2] = pk2(a, c);
        }
        if (tid < 64) bs[tid] = b0[tid];

        if (tid == 0) {
            unsigned target = (unsigned)(cbase + 16);
            for (;;) {
                unsigned v;
                asm volatile("ld.acquire.gpu.u32 %0, [%1];"
                             : "=r"(v) : "l"(g_prog + b) : "memory");
                if (v >= target) break;
                __nanosleep(1000);
            }
        }
        __syncthreads();
        if (tid < 48) {
            int d = tid >> 4, s = cbase + (tid & 15);
            cs[tid] = g_centers[(b*3 + d)*S_ + s];
        }
        __syncthreads();

        {
            float cx = cs[wid], cy = cs[16 + wid], cz = cs[32 + wid];
            float cn = __fadd_rn(__fadd_rn(__fmul_rn(cx,cx), __fmul_rn(cy,cy)), __fmul_rn(cz,cz));
            int found = 0, firstn = 0;
            int* op = ns + wid*KNB;
            for (int base = 0; base < N_; base += 32) {
                int n = base + lane;
                float x = __ldg(cb + n), y = __ldg(cb + N_ + n), z = __ldg(cb + 2*N_ + n);
                float pn = __fadd_rn(__fadd_rn(__fmul_rn(x,x), __fmul_rn(y,y)), __fmul_rn(z,z));
                float cp = __fadd_rn(__fadd_rn(__fmul_rn(cx,x), __fmul_rn(cy,y)), __fmul_rn(cz,z));
                float d2 = __fsub_rn(__fadd_rn(cn, pn), __fmul_rn(2.0f, cp));
                bool hit = d2 < 0.0625f;
                unsigned bal = __ballot_sync(0xffffffffu, hit);
                if (bal) {
                    if (found == 0) firstn = base + __ffs(bal) - 1;
                    int slot = found + __popc(bal & ((1u << lane) - 1u));
                    if (hit && slot < KNB) op[slot] = n;
                    found += __popc(bal);
                    if (found >= KNB) break;
                }
            }
            if (found < KNB) {
                int fill = (found > 0) ? firstn : 0;
                for (int sl = found + lane; sl < KNB; sl += 32) op[sl] = fill;
            }
        }
        __syncthreads();

        for (int tile = 0; tile < 2; tile++) {
            int pb2 = tile * 256;
            {
                int h = tid >> 8, pt = tid & 255;
                int lp = pb2 + pt;
                int sl = lp >> 5;
                int n = ns[sl*KNB + (lp & 31)];
                const float4* fp = (const float4*)(g_featT + ((size_t)b*N_ + n)*C_);
                if (h == 0) {
                    xs[0*256 + pt] = __fsub_rn(cb[n],        cs[sl]);
                    xs[1*256 + pt] = __fsub_rn(cb[N_ + n],   cs[16 + sl]);
                    xs[2*256 + pt] = __fsub_rn(cb[2*N_ + n], cs[32 + sl]);
#pragma unroll
                    for (int q = 0; q < 8; q++) {
                        float4 v = fp[q]; int ib = 3 + 4*q;
                        xs[(ib+0)*256 + pt] = v.x; xs[(ib+1)*256 + pt] = v.y;
                        xs[(ib+2)*256 + pt] = v.z; xs[(ib+3)*256 + pt] = v.w;
                    }
                } else {
#pragma unroll
                    for (int q = 8; q < 16; q++) {
                        float4 v = fp[q]; int ib = 3 + 4*q;
                        xs[(ib+0)*256 + pt] = v.x; xs[(ib+1)*256 + pt] = v.y;
                        xs[(ib+2)*256 + pt] = v.z; xs[(ib+3)*256 + pt] = v.w;
                    }
                    xs[67*256 + pt] = 0.0f;
                }
            }
            __syncthreads();

            int og  = tid >> 7;
            int pr  = tid & 127;
            int pt0 = pr * 2;
            ull acc0[8], acc1[8];
#pragma unroll
            for (int q = 0; q < 8; q++) {
                ull bv = pk2(bs[og*16 + 2*q], bs[og*16 + 2*q + 1]);
                acc0[q] = bv; acc1[q] = bv;
            }
#pragma unroll 2
            for (int i = 0; i < 68; i++) {
                ull xv = *(const ull*)(xs + i*256 + pt0);
                float x0, x1; upk2(xv, x0, x1);
                ull xx0 = pk2(x0, x0), xx1 = pk2(x1, x1);
                const ulonglong2* wr = (const ulonglong2*)(wp + i*32 + og*8);
#pragma unroll
                for (int q2 = 0; q2 < 4; q2++) {
                    ulonglong2 wq = wr[q2];
                    acc0[2*q2]   = fma2(wq.x, xx0, acc0[2*q2]);
                    acc1[2*q2]   = fma2(wq.x, xx1, acc1[2*q2]);
                    acc0[2*q2+1] = fma2(wq.y, xx0, acc0[2*q2+1]);
                    acc1[2*q2+1] = fma2(wq.y, xx1, acc1[2*q2+1]);
                }
            }
            float* yb = g_bufA + ((size_t)b*64)*PTS + cbase*KNB + pb2 + pt0;
#pragma unroll
            for (int q = 0; q < 8; q++) {
                int o = og*16 + 2*q;
                float a00, a01, a10, a11;
                upk2(acc0[q], a00, a01);
                upk2(acc1[q], a10, a11);
                *(float2*)(yb + (size_t)o*PTS)     = make_float2(a00, a10);
                *(float2*)(yb + (size_t)(o+1)*PTS) = make_float2(a01, a11);
            }
            __syncthreads();
        }
    }
}

/* ------------ per-(b,c) stats: deterministic two-stage ------------ */
template<int COUT, bool SRC_A>
__global__ void __launch_bounds__(256) k_stats(int off) {
    const float* y = SRC_A ? g_bufA : g_bufB;
    int bc = blockIdx.x;
    const float4* p4 = (const float4*)(y + (size_t)bc*PTS);
    float s = 0.0f, q = 0.0f;
    for (int i = threadIdx.x; i < PTS/4; i += 256) {
        float4 v = p4[i];
        s += v.x + v.y + v.z + v.w;
        q += v.x*v.x + v.y*v.y + v.z*v.z + v.w*v.w;
    }
    double ds = (double)s, dq = (double)q;
    int lane = threadIdx.x & 31, w = threadIdx.x >> 5;
#pragma unroll
    for (int o = 16; o; o >>= 1) {
        ds += __shfl_xor_sync(0xffffffffu, ds, o);
        dq += __shfl_xor_sync(0xffffffffu, dq, o);
    }
    __shared__ double sh[16];
    if (lane == 0) { sh[w] = ds; sh[8 + w] = dq; }
    __syncthreads();
    if (threadIdx.x == 0) {
        double S = 0.0, Q = 0.0;
#pragma unroll
        for (int i = 0; i < 8; i++) { S += sh[i]; Q += sh[8 + i]; }
        g_csum[off + bc] = S; g_csq[off + bc] = Q;
    }
}

/* ------------ convN64: GN + SiLU + (64->64), 256 thr, 8 og x 4 pts ------------ */
#define CONVN64_SMEM (64*128*4 + 64*32*8 + (64+64+64)*4)
__global__ void __launch_bounds__(256) k_convN64(const float* __restrict__ w,
                                                 const float* __restrict__ bb,
                                                 const float* __restrict__ gamma,
                                                 const float* __restrict__ beta,
                                                 int off, double inv_cnt) {
    extern __shared__ float sm[];
    float* xs = sm;                        /* [64][128] */
    ull*   wp = (ull*)(sm + 64*128);       /* [64][32] */
    float* bs = (float*)(wp + 64*32);
    float* al = bs + 64;
    float* bt = al + 64;
    int tid = threadIdx.x;
    int b = blockIdx.x >> 9;
    int pbase = (blockIdx.x & 511)*128;

    for (int k2 = tid; k2 < 64*32; k2 += 256) {
        int i = k2 >> 5, o2 = k2 & 31;
        wp[k2] = pk2(w[(2*o2)*64 + i], w[(2*o2+1)*64 + i]);
    }
    if (tid < 64) bs[tid] = bb[tid];
    if (tid < 64) {
        int g = tid >> 3;
        double ms = 0.0, qs = 0.0;
#pragma unroll
        for (int cc = 0; cc < 8; cc++) {
            ms += g_csum[off + b*64 + g*8 + cc];
            qs += g_csq [off + b*64 + g*8 + cc];
        }
        double mu  = ms * inv_cnt;
        double var = qs * inv_cnt - mu*mu;
        float rstd = (float)rsqrt(var + 1e-5);
        float a = gamma[tid] * rstd;
        al[tid] = a;
        bt[tid] = beta[tid] - (float)mu * a;
    }
    __syncthreads();

    {
        int h = tid >> 7, pt = tid & 127;
        int p = pbase + pt;
#pragma unroll 8
        for (int cc = 0; cc < 32; cc++) {
            int ci = h*32 + cc;
            float v  = g_bufA[((size_t)b*64 + ci)*PTS + p];
            float xn = fmaf(v, al[ci], bt[ci]);
            float sg = __fdividef(1.0f, 1.0f + __expf(-xn));
            xs[ci*128 + pt] = xn * sg;
        }
    }
    __syncthreads();

    int og  = tid >> 5;            /* 0..7: outputs og*8..og*8+7 */
    int pt0 = (tid & 31) * 4;
    ull acc[4][4];
#pragma unroll
    for (int q = 0; q < 4; q++) {
        ull bv = pk2(bs[og*8 + 2*q], bs[og*8 + 2*q + 1]);
        acc[0][q] = bv; acc[1][q] = bv; acc[2][q] = bv; acc[3][q] = bv;
    }
#pragma unroll 2
    for (int i = 0; i < 64; i++) {
        float4 xv = *(const float4*)(xs + i*128 + pt0);
        ull xx0 = pk2(xv.x, xv.x), xx1 = pk2(xv.y, xv.y);
        ull xx2 = pk2(xv.z, xv.z), xx3 = pk2(xv.w, xv.w);
        const ulonglong2* wr = (const ulonglong2*)(wp + i*32 + og*4);
#pragma unroll
        for (int q2 = 0; q2 < 2; q2++) {
            ulonglong2 wq = wr[q2];
            acc[0][2*q2]   = fma2(wq.x, xx0, acc[0][2*q2]);
            acc[1][2*q2]   = fma2(wq.x, xx1, acc[1][2*q2]);
            acc[2][2*q2]   = fma2(wq.x, xx2, acc[2][2*q2]);
            acc[3][2*q2]   = fma2(wq.x, xx3, acc[3][2*q2]);
            acc[0][2*q2+1] = fma2(wq.y, xx0, acc[0][2*q2+1]);
            acc[1][2*q2+1] = fma2(wq.y, xx1, acc[1][2*q2+1]);
            acc[2][2*q2+1] = fma2(wq.y, xx2, acc[2][2*q2+1]);
            acc[3][2*q2+1] = fma2(wq.y, xx3, acc[3][2*q2+1]);
        }
    }
    float* yb = g_bufB + ((size_t)b*64)*PTS + pbase + pt0;
#pragma unroll
    for (int q = 0; q < 4; q++) {
        int o = og*8 + 2*q;
        float a0l,a0h,a1l,a1h,a2l,a2h,a3l,a3h;
        upk2(acc[0][q],a0l,a0h); upk2(acc[1][q],a1l,a1h);
        upk2(acc[2][q],a2l,a2h); upk2(acc[3][q],a3l,a3h);
        *(float4*)(yb + (size_t)o*PTS)     = make_float4(a0l,a1l,a2l,a3l);
        *(float4*)(yb + (size_t)(o+1)*PTS) = make_float4(a0h,a1h,a2h,a3h);
    }
}

/* ------------ conv128: GN + SiLU + (64->128), 256 thr, 8 og x 4 pts ------------ */
#define CONV128_SMEM (64*128*4 + 64*64*8 + (128+64+64)*4)
__global__ void __launch_bounds__(256) k_conv128(const float* __restrict__ w,
                                                 const float* __restrict__ bb,
                                                 const float* __restrict__ gamma,
                                                 const float* __restrict__ beta,
                                                 int off, double inv_cnt) {
    extern __shared__ float sm[];
    float* xs = sm;                        /* [64][128] */
    ull*   wp = (ull*)(sm + 64*128);       /* [64][64] */
    float* bs = (float*)(wp + 64*64);      /* [128] */
    float* al = bs + 128;
    float* bt = al + 64;
    int tid = threadIdx.x;
    int b = blockIdx.x >> 9;
    int pbase = (blockIdx.x & 511)*128;

    for (int k2 = tid; k2 < 64*64; k2 += 256) {
        int i = k2 >> 6, o2 = k2 & 63;
        wp[k2] = pk2(w[(2*o2)*64 + i], w[(2*o2+1)*64 + i]);
    }
    if (tid < 128) bs[tid] = bb[tid];
    if (tid < 64) {
        int g = tid >> 3;
        double ms = 0.0, qs = 0.0;
#pragma unroll
        for (int cc = 0; cc < 8; cc++) {
            ms += g_csum[off + b*64 + g*8 + cc];
            qs += g_csq [off + b*64 + g*8 + cc];
        }
        double mu  = ms * inv_cnt;
        double var = qs * inv_cnt - mu*mu;
        float rstd = (float)rsqrt(var + 1e-5);
        float a = gamma[tid] * rstd;
        al[tid] = a;
        bt[tid] = beta[tid] - (float)mu * a;
    }
    __syncthreads();

    {
        int h = tid >> 7, pt = tid & 127;
        int p = pbase + pt;
#pragma unroll 8
        for (int cc = 0; cc < 32; cc++) {
            int ci = h*32 + cc;
            float v  = g_bufB[((size_t)b*64 + ci)*PTS + p];
            float xn = fmaf(v, al[ci], bt[ci]);
            float sg = __fdividef(1.0f, 1.0f + __expf(-xn));
            xs[ci*128 + pt] = xn * sg;
        }
    }
    __syncthreads();

    int og  = tid >> 5;            /* 0..7: outputs og*16..og*16+15 */
    int pt0 = (tid & 31) * 4;
    ull acc[4][8];
#pragma unroll
    for (int q = 0; q < 8; q++) {
        ull bv = pk2(bs[og*16 + 2*q], bs[og*16 + 2*q + 1]);
        acc[0][q] = bv; acc[1][q] = bv; acc[2][q] = bv; acc[3][q] = bv;
    }
#pragma unroll 2
    for (int i = 0; i < 64; i++) {
        float4 xv = *(const float4*)(xs + i*128 + pt0);
        ull xx0 = pk2(xv.x, xv.x), xx1 = pk2(xv.y, xv.y);
        ull xx2 = pk2(xv.z, xv.z), xx3 = pk2(xv.w, xv.w);
        const ulonglong2* wr = (const ulonglong2*)(wp + i*64 + og*8);
#pragma unroll
        for (int q2 = 0; q2 < 4; q2++) {
            ulonglong2 wq = wr[q2];
            acc[0][2*q2]   = fma2(wq.x, xx0, acc[0][2*q2]);
            acc[1][2*q2]   = fma2(wq.x, xx1, acc[1][2*q2]);
            acc[2][2*q2]   = fma2(wq.x, xx2, acc[2][2*q2]);
            acc[3][2*q2]   = fma2(wq.x, xx3, acc[3][2*q2]);
            acc[0][2*q2+1] = fma2(wq.y, xx0, acc[0][2*q2+1]);
            acc[1][2*q2+1] = fma2(wq.y, xx1, acc[1][2*q2+1]);
            acc[2][2*q2+1] = fma2(wq.y, xx2, acc[2][2*q2+1]);
            acc[3][2*q2+1] = fma2(wq.y, xx3, acc[3][2*q2+1]);
        }
    }
    float* yb = g_bufA + ((size_t)b*128)*PTS + pbase + pt0;
#pragma unroll
    for (int q = 0; q < 8; q++) {
        int o = og*16 + 2*q;
        float a0l,a0h,a1l,a1h,a2l,a2h,a3l,a3h;
        upk2(acc[0][q],a0l,a0h); upk2(acc[1][q],a1l,a1h);
        upk2(acc[2][q],a2l,a2h); upk2(acc[3][q],a3l,a3h);
        *(float4*)(yb + (size_t)o*PTS)     = make_float4(a0l,a1l,a2l,a3l);
        *(float4*)(yb + (size_t)(o+1)*PTS) = make_float4(a0h,a1h,a2h,a3h);
    }
}

/* ------------ final: GN + SiLU + max over K ------------ */
__global__ void __launch_bounds__(256) k_final(const float* __restrict__ gamma,
                                               const float* __restrict__ beta,
                                               float* __restrict__ out,
                                               int off, double inv_cnt) {
    int blk = blockIdx.x;
    int bc = blk >> 5;
    int chunk = blk & 31;
    int b = bc >> 7, c = bc & 127;
    __shared__ float s_a, s_b;
    if (threadIdx.x == 0) {
        int g = c >> 4;
        double ms = 0.0, qs = 0.0;
#pragma unroll
        for (int cc = 0; cc < 16; cc++) {
            ms += g_csum[off + b*128 + g*16 + cc];
            qs += g_csq [off + b*128 + g*16 + cc];
        }
        double mu  = ms * inv_cnt;
        double var = qs * inv_cnt - mu*mu;
        float rstd = (float)rsqrt(var + 1e-5);
        float a = gamma[c] * rstd;
        s_a = a;
        s_b = beta[c] - (float)mu * a;
    }
    __syncthreads();
    float a = s_a, bt = s_b;
    int w = threadIdx.x >> 5, lane = threadIdx.x & 31;
    const float* base = g_bufA + (size_t)bc*PTS;
#pragma unroll 4
    for (int j = 0; j < 8; j++) {
        int s = chunk*64 + w*8 + j;
        float v  = base[s*32 + lane];
        float xn = fmaf(v, a, bt);
        float sg = __fdividef(1.0f, 1.0f + __expf(-xn));
        float val = xn * sg;
#pragma unroll
        for (int o = 16; o; o >>= 1)
            val = fmaxf(val, __shfl_xor_sync(0xffffffffu, val, o));
        if (lane == 0) out[(size_t)bc*S_ + s] = val;
    }
}

extern "C" void kernel_launch(void* const* d_in, const int* in_sizes, int n_in,
                              void* d_out, int out_size) {
    const float* coords   = (const float*)d_in[0];
    const float* features = (const float*)d_in[1];
    const float* w0 = (const float*)d_in[2];
    const float* b0 = (const float*)d_in[3];
    const float* g0 = (const float*)d_in[4];
    const float* be0= (const float*)d_in[5];
    const float* w1 = (const float*)d_in[6];
    const float* b1 = (const float*)d_in[7];
    const float* g1 = (const float*)d_in[8];
    const float* be1= (const float*)d_in[9];
    const float* w2 = (const float*)d_in[10];
    const float* b2 = (const float*)d_in[11];
    const float* g2 = (const float*)d_in[12];
    const float* be2= (const float*)d_in[13];
    float* out = (float*)d_out;

    cudaFuncSetAttribute(k_fused,   cudaFuncAttributeMaxDynamicSharedMemorySize, FUSED_SMEM);
    cudaFuncSetAttribute(k_convN64, cudaFuncAttributeMaxDynamicSharedMemorySize, CONVN64_SMEM);
    cudaFuncSetAttribute(k_conv128, cudaFuncAttributeMaxDynamicSharedMemorySize, CONV128_SMEM);

    dim3 tg(N_/32, C_/32, B_);
    k_transpose<<<tg, dim3(32,8)>>>(features);
    k_fused<<<8 + B_*128, 512, FUSED_SMEM>>>(coords, w0, b0);
    k_stats<64,true><<<B_*64, 256>>>(0);
    k_convN64<<<B_*512, 256, CONVN64_SMEM>>>(w1, b1, g0, be0, 0, 1.0/(8.0*PTS));
    k_stats<64,false><<<B_*64, 256>>>(512);
    k_conv128<<<B_*512, 256, CONV128_SMEM>>>(w2, b2, g1, be1, 512, 1.0/(8.0*PTS));
    k_stats<128,true><<<B_*128, 256>>>(1024);
    k_final<<<B_*128*32, 256>>>(g2, be2, out, 1024, 1.0/(16.0*PTS));
}

// round 17
// speedup vs baseline: 1.2462x; 1.0079x over previous
#include <cuda_runtime.h>
#include <math.h>
#include <stdint.h>

#define B_  8
#define N_  8192
#define C_  64
#define S_  2048
#define KNB 32
#define PTS (S_*KNB)
typedef unsigned long long ull;

__device__ float    g_featT[(size_t)B_*N_*C_];
__device__ float    g_centers[B_*3*S_];
__device__ float    g_bufA[(size_t)B_*128*PTS];
__device__ float    g_bufB[(size_t)B_*128*PTS];
__device__ float    g_partS[512*256];
__device__ float    g_partQ[512*256];
__device__ double   g_csum[2048];
__device__ double   g_csq [2048];
__device__ unsigned g_prog[8];

__device__ __forceinline__ ull pk2(float lo, float hi) {
    ull r; asm("mov.b64 %0,{%1,%2};" : "=l"(r) : "f"(lo), "f"(hi)); return r;
}
__device__ __forceinline__ void upk2(ull v, float& lo, float& hi) {
    asm("mov.b64 {%0,%1},%2;" : "=f"(lo), "=f"(hi) : "l"(v));
}
__device__ __forceinline__ ull add2(ull a, ull b) {
    ull r; asm("add.rn.f32x2 %0,%1,%2;" : "=l"(r) : "l"(a), "l"(b)); return r;
}
__device__ __forceinline__ ull mul2(ull a, ull b) {
    ull r; asm("mul.rn.f32x2 %0,%1,%2;" : "=l"(r) : "l"(a), "l"(b)); return r;
}
__device__ __forceinline__ ull fma2(ull a, ull b, ull c) {
    ull r; asm("fma.rn.f32x2 %0,%1,%2,%3;" : "=l"(r) : "l"(a), "l"(b), "l"(c)); return r;
}

/* ------------ transpose features [b][c][n] -> [b][n][c] ------------ */
__global__ void k_transpose(const float* __restrict__ f) {
    __shared__ float t[32][33];
    int b = blockIdx.z;
    int nb = blockIdx.x * 32, cb = blockIdx.y * 32;
    int tx = threadIdx.x, ty = threadIdx.y;
#pragma unroll
    for (int j = 0; j < 32; j += 8)
        t[ty + j][tx] = f[((size_t)b*C_ + cb + ty + j)*N_ + nb + tx];
    __syncthreads();
#pragma unroll
    for (int j = 0; j < 32; j += 8)
        g_featT[((size_t)b*N_ + nb + ty + j)*C_ + cb + tx] = t[tx][ty + j];
}

/* ------------ fused: FPS (blocks 0-7) + ball/conv0/stats workers ------------ */
#define FUSED_SMEM (3*N_*4 + 64*4)
__global__ void __launch_bounds__(512, 1) k_fused(const float* __restrict__ coords,
                                                  const float* __restrict__ w0,
                                                  const float* __restrict__ b0) {
    extern __shared__ float sm[];
    int tid = threadIdx.x;
    int lane = tid & 31, wid = tid >> 5;

    if (blockIdx.x < 8) {
        /* ================= FPS producer ================= */
        float* sx = sm; float* sy = sm + N_; float* sz = sm + 2*N_;
        unsigned* wbv = (unsigned*)(sm + 3*N_);
        unsigned* wbn = wbv + 32;
        int b = blockIdx.x;
        const float* cb = coords + (size_t)b*3*N_;

        ull pxp[8], pyp[8], pzp[8];
        float mind[16];
#pragma unroll
        for (int jj = 0; jj < 8; jj++) {
            int n0 = (2*jj)*512 + tid, n1 = n0 + 512;
            float x0 = cb[n0],        x1 = cb[n1];
            float y0 = cb[N_ + n0],   y1 = cb[N_ + n1];
            float z0 = cb[2*N_ + n0], z1 = cb[2*N_ + n1];
            sx[n0] = x0; sx[n1] = x1;
            sy[n0] = y0; sy[n1] = y1;
            sz[n0] = z0; sz[n1] = z1;
            pxp[jj] = pk2(x0, x1); pyp[jj] = pk2(y0, y1); pzp[jj] = pk2(z0, z1);
            mind[2*jj] = 1e10f; mind[2*jj+1] = 1e10f;
        }
        float lx = cb[0], ly = cb[N_], lz = cb[2*N_];
        if (tid == 0) {
            g_centers[(b*3+0)*S_] = lx;
            g_centers[(b*3+1)*S_] = ly;
            g_centers[(b*3+2)*S_] = lz;
        }
        __syncthreads();

        for (int step = 1; step < S_; ++step) {
            ull nlx = pk2(-lx, -lx), nly = pk2(-ly, -ly), nlz = pk2(-lz, -lz);
            float bd = -1.0f;
#pragma unroll
            for (int jj = 0; jj < 8; jj++) {
                ull dx = add2(pxp[jj], nlx);
                ull dy = add2(pyp[jj], nly);
                ull dz = add2(pzp[jj], nlz);
                ull s  = mul2(dx, dx);
                ull t  = mul2(dy, dy);
                s = add2(s, t);
                t = mul2(dz, dz);
                s = add2(s, t);
                float d0, d1; upk2(s, d0, d1);
                float m0 = fminf(mind[2*jj],   d0); mind[2*jj]   = m0;
                float m1 = fminf(mind[2*jj+1], d1); mind[2*jj+1] = m1;
                bd = fmaxf(bd, m0);
                bd = fmaxf(bd, m1);
            }
            unsigned bdb = __float_as_uint(bd);
            unsigned wv  = __reduce_max_sync(0xffffffffu, bdb);
            unsigned cand = 0xffffffffu;
            if (bdb == wv) {
#pragma unroll
                for (int j = 15; j >= 0; j--)
                    if (__float_as_uint(mind[j]) == wv)
                        cand = (unsigned)(j*512 + tid);
            }
            unsigned wn = __reduce_min_sync(0xffffffffu, cand);
            int pb = (step & 1) * 16;
            if (lane == 0) { wbv[pb + wid] = wv; wbn[pb + wid] = wn; }
            __syncthreads();
            unsigned v  = wbv[pb + (lane & 15)];
            unsigned nn = wbn[pb + (lane & 15)];
            unsigned vm = __reduce_max_sync(0xffffffffu, v);
            unsigned c2 = (v == vm) ? nn : 0xffffffffu;
            unsigned win = __reduce_min_sync(0xffffffffu, c2);
            lx = sx[win]; ly = sy[win]; lz = sz[win];
            if (tid == 0) {
                g_centers[(b*3+0)*S_ + step] = lx;
                g_centers[(b*3+1)*S_ + step] = ly;
                g_centers[(b*3+2)*S_ + step] = lz;
                if ((step & 15) == 15) {
                    unsigned pv = (unsigned)(step + 1);
                    asm volatile("st.release.gpu.u32 [%0], %1;"
                                 :: "l"(g_prog + b), "r"(pv) : "memory");
                }
            }
        }
    } else {
        /* ================= ball + conv0 + stats consumer ================= */
        int w = blockIdx.x - 8;
        int b = w & 7;
        int wkr = w >> 3;
        int cbase = wkr * 16;
        float* xs = sm;                     /* [68][256] */
        ull*   wp = (ull*)(sm + 68*256);    /* [68][32] */
        float* bs = (float*)(wp + 68*32);   /* [64] */
        float* cs = bs + 64;                /* [3][16] */
        int*   ns = (int*)(cs + 48);        /* [16][32] */
        const float* cb = coords + (size_t)b*3*N_;

        for (int k2 = tid; k2 < 68*32; k2 += 512) {
            int i = k2 >> 5, o2 = k2 & 31;
            float a = (i < 67) ? w0[(2*o2)*67 + i]   : 0.0f;
            float c = (i < 67) ? w0[(2*o2+1)*67 + i] : 0.0f;
            wp[k2] = pk2(a, c);
        }
        if (tid < 64) bs[tid] = b0[tid];

        if (tid == 0) {
            unsigned target = (unsigned)(cbase + 16);
            for (;;) {
                unsigned v;
                asm volatile("ld.acquire.gpu.u32 %0, [%1];"
                             : "=r"(v) : "l"(g_prog + b) : "memory");
                if (v >= target) break;
                __nanosleep(1000);
            }
        }
        __syncthreads();
        if (tid < 48) {
            int d = tid >> 4, s = cbase + (tid & 15);
            cs[tid] = g_centers[(b*3 + d)*S_ + s];
        }
        __syncthreads();

        {
            float cx = cs[wid], cy = cs[16 + wid], cz = cs[32 + wid];
            float cn = __fadd_rn(__fadd_rn(__fmul_rn(cx,cx), __fmul_rn(cy,cy)), __fmul_rn(cz,cz));
            int found = 0, firstn = 0;
            int* op = ns + wid*KNB;
            for (int base = 0; base < N_; base += 32) {
                int n = base + lane;
                float x = __ldg(cb + n), y = __ldg(cb + N_ + n), z = __ldg(cb + 2*N_ + n);
                float pn = __fadd_rn(__fadd_rn(__fmul_rn(x,x), __fmul_rn(y,y)), __fmul_rn(z,z));
                float cp = __fadd_rn(__fadd_rn(__fmul_rn(cx,x), __fmul_rn(cy,y)), __fmul_rn(cz,z));
                float d2 = __fsub_rn(__fadd_rn(cn, pn), __fmul_rn(2.0f, cp));
                bool hit = d2 < 0.0625f;
                unsigned bal = __ballot_sync(0xffffffffu, hit);
                if (bal) {
                    if (found == 0) firstn = base + __ffs(bal) - 1;
                    int slot = found + __popc(bal & ((1u << lane) - 1u));
                    if (hit && slot < KNB) op[slot] = n;
                    found += __popc(bal);
                    if (found >= KNB) break;
                }
            }
            if (found < KNB) {
                int fill = (found > 0) ? firstn : 0;
                for (int sl = found + lane; sl < KNB; sl += 32) op[sl] = fill;
            }
        }
        __syncthreads();

        for (int tile = 0; tile < 2; tile++) {
            int pb2 = tile * 256;
            {
                int h = tid >> 8, pt = tid & 255;
                int lp = pb2 + pt;
                int sl = lp >> 5;
                int n = ns[sl*KNB + (lp & 31)];
                const float4* fp = (const float4*)(g_featT + ((size_t)b*N_ + n)*C_);
                if (h == 0) {
                    xs[0*256 + pt] = __fsub_rn(cb[n],        cs[sl]);
                    xs[1*256 + pt] = __fsub_rn(cb[N_ + n],   cs[16 + sl]);
                    xs[2*256 + pt] = __fsub_rn(cb[2*N_ + n], cs[32 + sl]);
#pragma unroll
                    for (int q = 0; q < 8; q++) {
                        float4 v = fp[q]; int ib = 3 + 4*q;
                        xs[(ib+0)*256 + pt] = v.x; xs[(ib+1)*256 + pt] = v.y;
                        xs[(ib+2)*256 + pt] = v.z; xs[(ib+3)*256 + pt] = v.w;
                    }
                } else {
#pragma unroll
                    for (int q = 8; q < 16; q++) {
                        float4 v = fp[q]; int ib = 3 + 4*q;
                        xs[(ib+0)*256 + pt] = v.x; xs[(ib+1)*256 + pt] = v.y;
                        xs[(ib+2)*256 + pt] = v.z; xs[(ib+3)*256 + pt] = v.w;
                    }
                    xs[67*256 + pt] = 0.0f;
                }
            }
            __syncthreads();

            int og  = tid >> 7;
            int pr  = tid & 127;
            int pt0 = pr * 2;
            ull acc0[8], acc1[8];
#pragma unroll
            for (int q = 0; q < 8; q++) {
                ull bv = pk2(bs[og*16 + 2*q], bs[og*16 + 2*q + 1]);
                acc0[q] = bv; acc1[q] = bv;
            }
#pragma unroll 2
            for (int i = 0; i < 68; i++) {
                ull xv = *(const ull*)(xs + i*256 + pt0);
                float x0, x1; upk2(xv, x0, x1);
                ull xx0 = pk2(x0, x0), xx1 = pk2(x1, x1);
                const ulonglong2* wr = (const ulonglong2*)(wp + i*32 + og*8);
#pragma unroll
                for (int q2 = 0; q2 < 4; q2++) {
                    ulonglong2 wq = wr[q2];
                    acc0[2*q2]   = fma2(wq.x, xx0, acc0[2*q2]);
                    acc1[2*q2]   = fma2(wq.x, xx1, acc1[2*q2]);
                    acc0[2*q2+1] = fma2(wq.y, xx0, acc0[2*q2+1]);
                    acc1[2*q2+1] = fma2(wq.y, xx1, acc1[2*q2+1]);
                }
            }
            float* yb = g_bufA + ((size_t)b*64)*PTS + cbase*KNB + pb2 + pt0;
#pragma unroll
            for (int q = 0; q < 8; q++) {
                int o = og*16 + 2*q;
                float a00, a01, a10, a11;
                upk2(acc0[q], a00, a01);
                upk2(acc1[q], a10, a11);
                *(float2*)(yb + (size_t)o*PTS)     = make_float2(a00, a10);
                *(float2*)(yb + (size_t)(o+1)*PTS) = make_float2(a01, a11);
            }
            __syncthreads();

            /* ---- free stats: partials into dead xs, reduce, one float/(ch,wkr,tile) ---- */
            float* psS = sm;                 /* [64][128] skewed */
            float* psQ = sm + 8192;
#pragma unroll
            for (int q = 0; q < 8; q++) {
                int o = og*16 + 2*q;
                ull sp = add2(acc0[q], acc1[q]);
                ull m  = mul2(acc0[q], acc0[q]);
                ull qp = fma2(acc1[q], acc1[q], m);
                float sl, sh2, ql, qh;
                upk2(sp, sl, sh2); upk2(qp, ql, qh);
                psS[o*128     + ((pr + o)     & 127)] = sl;
                psS[(o+1)*128 + ((pr + o + 1) & 127)] = sh2;
                psQ[o*128     + ((pr + o)     & 127)] = ql;
                psQ[(o+1)*128 + ((pr + o + 1) & 127)] = qh;
            }
            __syncthreads();
            if (tid < 64) {
                float ss = 0.0f, qq = 0.0f;
                for (int k = 0; k < 128; k++) {
                    int col = (k + tid) & 127;
                    ss += psS[tid*128 + col];
                    qq += psQ[tid*128 + col];
                }
                g_partS[(size_t)(b*64 + tid)*256 + wkr*2 + tile] = ss;
                g_partQ[(size_t)(b*64 + tid)*256 + wkr*2 + tile] = qq;
            }
            __syncthreads();
        }
    }
}

/* ------------ k_red0: 256 worker-partials -> g_csum/g_csq[0..511] ------------ */
__global__ void __launch_bounds__(256) k_red0() {
    int bc = blockIdx.x;
    int t = threadIdx.x;
    double ds = (double)g_partS[(size_t)bc*256 + t];
    double dq = (double)g_partQ[(size_t)bc*256 + t];
    int lane = t & 31, w = t >> 5;
#pragma unroll
    for (int o = 16; o; o >>= 1) {
        ds += __shfl_xor_sync(0xffffffffu, ds, o);
        dq += __shfl_xor_sync(0xffffffffu, dq, o);
    }
    __shared__ double sh[16];
    if (lane == 0) { sh[w] = ds; sh[8 + w] = dq; }
    __syncthreads();
    if (t == 0) {
        double S = 0.0, Q = 0.0;
#pragma unroll
        for (int i = 0; i < 8; i++) { S += sh[i]; Q += sh[8 + i]; }
        g_csum[bc] = S; g_csq[bc] = Q;
    }
}

/* ------------ per-(b,c) stats: deterministic two-stage ------------ */
template<int COUT, bool SRC_A>
__global__ void __launch_bounds__(256) k_stats(int off) {
    const float* y = SRC_A ? g_bufA : g_bufB;
    int bc = blockIdx.x;
    const float4* p4 = (const float4*)(y + (size_t)bc*PTS);
    float s = 0.0f, q = 0.0f;
    for (int i = threadIdx.x; i < PTS/4; i += 256) {
        float4 v = p4[i];
        s += v.x + v.y + v.z + v.w;
        q += v.x*v.x + v.y*v.y + v.z*v.z + v.w*v.w;
    }
    double ds = (double)s, dq = (double)q;
    int lane = threadIdx.x & 31, w = threadIdx.x >> 5;
#pragma unroll
    for (int o = 16; o; o >>= 1) {
        ds += __shfl_xor_sync(0xffffffffu, ds, o);
        dq += __shfl_xor_sync(0xffffffffu, dq, o);
    }
    __shared__ double sh[16];
    if (lane == 0) { sh[w] = ds; sh[8 + w] = dq; }
    __syncthreads();
    if (threadIdx.x == 0) {
        double S = 0.0, Q = 0.0;
#pragma unroll
        for (int i = 0; i < 8; i++) { S += sh[i]; Q += sh[8 + i]; }
        g_csum[off + bc] = S; g_csq[off + bc] = Q;
    }
}

/* ------------ convN64: GN + SiLU + (64->64), 256 thr, 8 og x 4 pts ------------ */
#define CONVN64_SMEM (64*128*4 + 64*32*8 + (64+64+64)*4)
__global__ void __launch_bounds__(256) k_convN64(const float* __restrict__ w,
                                                 const float* __restrict__ bb,
                                                 const float* __restrict__ gamma,
                                                 const float* __restrict__ beta,
                                                 int off, double inv_cnt) {
    extern __shared__ float sm[];
    float* xs = sm;                        /* [64][128] */
    ull*   wp = (ull*)(sm + 64*128);       /* [64][32] */
    float* bs = (float*)(wp + 64*32);
    float* al = bs + 64;
    float* bt = al + 64;
    int tid = threadIdx.x;
    int b = blockIdx.x >> 9;
    int pbase = (blockIdx.x & 511)*128;

    for (int k2 = tid; k2 < 64*32; k2 += 256) {
        int i = k2 >> 5, o2 = k2 & 31;
        wp[k2] = pk2(w[(2*o2)*64 + i], w[(2*o2+1)*64 + i]);
    }
    if (tid < 64) bs[tid] = bb[tid];
    if (tid < 64) {
        int g = tid >> 3;
        double ms = 0.0, qs = 0.0;
#pragma unroll
        for (int cc = 0; cc < 8; cc++) {
            ms += g_csum[off + b*64 + g*8 + cc];
            qs += g_csq [off + b*64 + g*8 + cc];
        }
        double mu  = ms * inv_cnt;
        double var = qs * inv_cnt - mu*mu;
        float rstd = (float)rsqrt(var + 1e-5);
        float a = gamma[tid] * rstd;
        al[tid] = a;
        bt[tid] = beta[tid] - (float)mu * a;
    }
    __syncthreads();

    {
        int h = tid >> 7, pt = tid & 127;
        int p = pbase + pt;
#pragma unroll 8
        for (int cc = 0; cc < 32; cc++) {
            int ci = h*32 + cc;
            float v  = g_bufA[((size_t)b*64 + ci)*PTS + p];
            float xn = fmaf(v, al[ci], bt[ci]);
            float sg = __fdividef(1.0f, 1.0f + __expf(-xn));
            xs[ci*128 + pt] = xn * sg;
        }
    }
    __syncthreads();

    int og  = tid >> 5;
    int pt0 = (tid & 31) * 4;
    ull acc[4][4];
#pragma unroll
    for (int q = 0; q < 4; q++) {
        ull bv = pk2(bs[og*8 + 2*q], bs[og*8 + 2*q + 1]);
        acc[0][q] = bv; acc[1][q] = bv; acc[2][q] = bv; acc[3][q] = bv;
    }
#pragma unroll 2
    for (int i = 0; i < 64; i++) {
        float4 xv = *(const float4*)(xs + i*128 + pt0);
        ull xx0 = pk2(xv.x, xv.x), xx1 = pk2(xv.y, xv.y);
        ull xx2 = pk2(xv.z, xv.z), xx3 = pk2(xv.w, xv.w);
        const ulonglong2* wr = (const ulonglong2*)(wp + i*32 + og*4);
#pragma unroll
        for (int q2 = 0; q2 < 2; q2++) {
            ulonglong2 wq = wr[q2];
            acc[0][2*q2]   = fma2(wq.x, xx0, acc[0][2*q2]);
            acc[1][2*q2]   = fma2(wq.x, xx1, acc[1][2*q2]);
            acc[2][2*q2]   = fma2(wq.x, xx2, acc[2][2*q2]);
            acc[3][2*q2]   = fma2(wq.x, xx3, acc[3][2*q2]);
            acc[0][2*q2+1] = fma2(wq.y, xx0, acc[0][2*q2+1]);
            acc[1][2*q2+1] = fma2(wq.y, xx1, acc[1][2*q2+1]);
            acc[2][2*q2+1] = fma2(wq.y, xx2, acc[2][2*q2+1]);
            acc[3][2*q2+1] = fma2(wq.y, xx3, acc[3][2*q2+1]);
        }
    }
    float* yb = g_bufB + ((size_t)b*64)*PTS + pbase + pt0;
#pragma unroll
    for (int q = 0; q < 4; q++) {
        int o = og*8 + 2*q;
        float a0l,a0h,a1l,a1h,a2l,a2h,a3l,a3h;
        upk2(acc[0][q],a0l,a0h); upk2(acc[1][q],a1l,a1h);
        upk2(acc[2][q],a2l,a2h); upk2(acc[3][q],a3l,a3h);
        *(float4*)(yb + (size_t)o*PTS)     = make_float4(a0l,a1l,a2l,a3l);
        *(float4*)(yb + (size_t)(o+1)*PTS) = make_float4(a0h,a1h,a2h,a3h);
    }
}

/* ------------ conv128: GN + SiLU + (64->128), 256 thr, 8 og x 4 pts ------------ */
#define CONV128_SMEM (64*128*4 + 64*64*8 + (128+64+64)*4)
__global__ void __launch_bounds__(256) k_conv128(const float* __restrict__ w,
                                                 const float* __restrict__ bb,
                                                 const float* __restrict__ gamma,
                                                 const float* __restrict__ beta,
                                                 int off, double inv_cnt) {
    extern __shared__ float sm[];
    float* xs = sm;                        /* [64][128] */
    ull*   wp = (ull*)(sm + 64*128);       /* [64][64] */
    float* bs = (float*)(wp + 64*64);      /* [128] */
    float* al = bs + 128;
    float* bt = al + 64;
    int tid = threadIdx.x;
    int b = blockIdx.x >> 9;
    int pbase = (blockIdx.x & 511)*128;

    for (int k2 = tid; k2 < 64*64; k2 += 256) {
        int i = k2 >> 6, o2 = k2 & 63;
        wp[k2] = pk2(w[(2*o2)*64 + i], w[(2*o2+1)*64 + i]);
    }
    if (tid < 128) bs[tid] = bb[tid];
    if (tid < 64) {
        int g = tid >> 3;
        double ms = 0.0, qs = 0.0;
#pragma unroll
        for (int cc = 0; cc < 8; cc++) {
            ms += g_csum[off + b*64 + g*8 + cc];
            qs += g_csq [off + b*64 + g*8 + cc];
        }
        double mu  = ms * inv_cnt;
        double var = qs * inv_cnt - mu*mu;
        float rstd = (float)rsqrt(var + 1e-5);
        float a = gamma[tid] * rstd;
        al[tid] = a;
        bt[tid] = beta[tid] - (float)mu * a;
    }
    __syncthreads();

    {
        int h = tid >> 7, pt = tid & 127;
        int p = pbase + pt;
#pragma unroll 8
        for (int cc = 0; cc < 32; cc++) {
            int ci = h*32 + cc;
            float v  = g_bufB[((size_t)b*64 + ci)*PTS + p];
            float xn = fmaf(v, al[ci], bt[ci]);
            float sg = __fdividef(1.0f, 1.0f + __expf(-xn));
            xs[ci*128 + pt] = xn * sg;
        }
    }
    __syncthreads();

    int og  = tid >> 5;
    int pt0 = (tid & 31) * 4;
    ull acc[4][8];
#pragma unroll
    for (int q = 0; q < 8; q++) {
        ull bv = pk2(bs[og*16 + 2*q], bs[og*16 + 2*q + 1]);
        acc[0][q] = bv; acc[1][q] = bv; acc[2][q] = bv; acc[3][q] = bv;
    }
#pragma unroll 2
    for (int i = 0; i < 64; i++) {
        float4 xv = *(const float4*)(xs + i*128 + pt0);
        ull xx0 = pk2(xv.x, xv.x), xx1 = pk2(xv.y, xv.y);
        ull xx2 = pk2(xv.z, xv.z), xx3 = pk2(xv.w, xv.w);
        const ulonglong2* wr = (const ulonglong2*)(wp + i*64 + og*8);
#pragma unroll
        for (int q2 = 0; q2 < 4; q2++) {
            ulonglong2 wq = wr[q2];
            acc[0][2*q2]   = fma2(wq.x, xx0, acc[0][2*q2]);
            acc[1][2*q2]   = fma2(wq.x, xx1, acc[1][2*q2]);
            acc[2][2*q2]   = fma2(wq.x, xx2, acc[2][2*q2]);
            acc[3][2*q2]   = fma2(wq.x, xx3, acc[3][2*q2]);
            acc[0][2*q2+1] = fma2(wq.y, xx0, acc[0][2*q2+1]);
            acc[1][2*q2+1] = fma2(wq.y, xx1, acc[1][2*q2+1]);
            acc[2][2*q2+1] = fma2(wq.y, xx2, acc[2][2*q2+1]);
            acc[3][2*q2+1] = fma2(wq.y, xx3, acc[3][2*q2+1]);
        }
    }
    float* yb = g_bufA + ((size_t)b*128)*PTS + pbase + pt0;
#pragma unroll
    for (int q = 0; q < 8; q++) {
        int o = og*16 + 2*q;
        float a0l,a0h,a1l,a1h,a2l,a2h,a3l,a3h;
        upk2(acc[0][q],a0l,a0h); upk2(acc[1][q],a1l,a1h);
        upk2(acc[2][q],a2l,a2h); upk2(acc[3][q],a3l,a3h);
        *(float4*)(yb + (size_t)o*PTS)     = make_float4(a0l,a1l,a2l,a3l);
        *(float4*)(yb + (size_t)(o+1)*PTS) = make_float4(a0h,a1h,a2h,a3h);
    }
}

/* ------------ final: GN + SiLU + max over K ------------ */
__global__ void __launch_bounds__(256) k_final(const float* __restrict__ gamma,
                                               const float* __restrict__ beta,
                                               float* __restrict__ out,
                                               int off, double inv_cnt) {
    int blk = blockIdx.x;
    int bc = blk >> 5;
    int chunk = blk & 31;
    int b = bc >> 7, c = bc & 127;
    __shared__ float s_a, s_b;
    if (threadIdx.x == 0) {
        int g = c >> 4;
        double ms = 0.0, qs = 0.0;
#pragma unroll
        for (int cc = 0; cc < 16; cc++) {
            ms += g_csum[off + b*128 + g*16 + cc];
            qs += g_csq [off + b*128 + g*16 + cc];
        }
        double mu  = ms * inv_cnt;
        double var = qs * inv_cnt - mu*mu;
        float rstd = (float)rsqrt(var + 1e-5);
        float a = gamma[c] * rstd;
        s_a = a;
        s_b = beta[c] - (float)mu * a;
    }
    __syncthreads();
    float a = s_a, bt = s_b;
    int w = threadIdx.x >> 5, lane = threadIdx.x & 31;
    const float* base = g_bufA + (size_t)bc*PTS;
#pragma unroll 4
    for (int j = 0; j < 8; j++) {
        int s = chunk*64 + w*8 + j;
        float v  = base[s*32 + lane];
        float xn = fmaf(v, a, bt);
        float sg = __fdividef(1.0f, 1.0f + __expf(-xn));
        float val = xn * sg;
#pragma unroll
        for (int o = 16; o; o >>= 1)
            val = fmaxf(val, __shfl_xor_sync(0xffffffffu, val, o));
        if (lane == 0) out[(size_t)bc*S_ + s] = val;
    }
}

extern "C" void kernel_launch(void* const* d_in, const int* in_sizes, int n_in,
                              void* d_out, int out_size) {
    const float* coords   = (const float*)d_in[0];
    const float* features = (const float*)d_in[1];
    const float* w0 = (const float*)d_in[2];
    const float* b0 = (const float*)d_in[3];
    const float* g0 = (const float*)d_in[4];
    const float* be0= (const float*)d_in[5];
    const float* w1 = (const float*)d_in[6];
    const float* b1 = (const float*)d_in[7];
    const float* g1 = (const float*)d_in[8];
    const float* be1= (const float*)d_in[9];
    const float* w2 = (const float*)d_in[10];
    const float* b2 = (const float*)d_in[11];
    const float* g2 = (const float*)d_in[12];
    const float* be2= (const float*)d_in[13];
    float* out = (float*)d_out;

    cudaFuncSetAttribute(k_fused,   cudaFuncAttributeMaxDynamicSharedMemorySize, FUSED_SMEM);
    cudaFuncSetAttribute(k_convN64, cudaFuncAttributeMaxDynamicSharedMemorySize, CONVN64_SMEM);
    cudaFuncSetAttribute(k_conv128, cudaFuncAttributeMaxDynamicSharedMemorySize, CONV128_SMEM);

    dim3 tg(N_/32, C_/32, B_);
    k_transpose<<<tg, dim3(32,8)>>>(features);
    k_fused<<<8 + B_*128, 512, FUSED_SMEM>>>(coords, w0, b0);
    k_red0<<<512, 256>>>();
    k_convN64<<<B_*512, 256, CONVN64_SMEM>>>(w1, b1, g0, be0, 0, 1.0/(8.0*PTS));
    k_stats<64,false><<<B_*64, 256>>>(512);
    k_conv128<<<B_*512, 256, CONV128_SMEM>>>(w2, b2, g1, be1, 512, 1.0/(8.0*PTS));
    k_stats<128,true><<<B_*128, 256>>>(1024);
    k_final<<<B_*128*32, 256>>>(g2, be2, out, 1024, 1.0/(16.0*PTS));
}